// round 1
// baseline (speedup 1.0000x reference)
#include <cuda_runtime.h>
#include <cuda_bf16.h>
#include <cstdint>
#include <cstddef>

// Problem constants
#define BB   32
#define NE   512
#define ND   512
#define VOC  2000
#define HH   256
#define FF   256
#define PP   4
#define EE   128

// ---------------- scratch (device globals; no allocations allowed) ----------------
__device__ float    g_epad[(size_t)BB * 516 * FF];        // padded tanh(embed) for conv
__device__ float    g_t[(size_t)BB * NE * FF];            // tanh(conv)
__device__ float    g_logits[(size_t)BB * NE * VOC];      // decode logits
__device__ float    g_rmax[BB * NE];
__device__ float    g_rsum[BB * NE];
__device__ float    g_S[(size_t)BB * ND * NE];            // encoder_scores, layout (b, j, i)
__device__ float    g_xemb[(size_t)BB * NE * EE];
__device__ float    g_yemb[(size_t)BB * ND * EE];
__device__ float    g_xz[(size_t)BB * NE * 4 * HH];       // x @ Wih^T + b
__device__ float    g_yz[(size_t)BB * ND * 4 * HH];
__device__ unsigned g_WencP[128 * 1024];                  // Whh packed bf16x2, [k2][n]
__device__ unsigned g_WdecP[128 * 1024];
__device__ float    g_hcat[(size_t)BB * NE * 2 * HH];     // [henc | hback]
__device__ float    g_cT[BB * HH];
__device__ float    g_hdec[(size_t)BB * ND * HH];         // shifted decoder states
__device__ float    g_Th[(size_t)BB * NE * HH];
__device__ float    g_E[(size_t)BB * ND * NE];            // eij, layout (b, j, i)
__device__ float    g_p[BB * ND];

// ---------------- generic fp32 tiled GEMM: C = A @ B (or A @ B^T) ----------------
// 128x128 tile, BK=8, 256 threads, 8x8 per thread.
// EPI: 0 none, 1 tanh, 2 +bias
template <int EPI, bool TB>
__global__ void __launch_bounds__(256) sgemm(
    const float* __restrict__ A, size_t sAz, int lda,
    const float* __restrict__ B, size_t sBz, int ldb,
    float* __restrict__ C, size_t sCz, int ldc,
    int M, int N, int K, const float* __restrict__ bias)
{
    __shared__ __align__(16) float As[8 * 128];
    __shared__ __align__(16) float Bs[8 * 128];

    const float* Ab = A + blockIdx.z * sAz;
    const float* Bb = B + blockIdx.z * sBz;
    float* Cb = C + blockIdx.z * sCz;

    const int bm0 = blockIdx.y * 128;
    const int bn0 = blockIdx.x * 128;
    const int tid = threadIdx.x;
    const int tx = tid & 15, ty = tid >> 4;

    float acc[8][8];
#pragma unroll
    for (int r = 0; r < 8; r++)
#pragma unroll
        for (int c = 0; c < 8; c++) acc[r][c] = 0.f;

    const int aRow = tid >> 1;            // 0..127
    const int aCol = (tid & 1) * 4;       // 0 or 4
    const int bRowNN = tid >> 5;          // 0..7  (k)
    const int bColNN = (tid & 31) * 4;    // 0..124
    const int bRowNT = tid >> 1;          // n 0..127
    const int bColNT = (tid & 1) * 4;     // k 0 or 4

    for (int k0 = 0; k0 < K; k0 += 8) {
        // --- load A tile (transposed into As[k][m]) ---
        float4 av = make_float4(0.f, 0.f, 0.f, 0.f);
        int am = bm0 + aRow;
        if (am < M) av = *(const float4*)(Ab + (size_t)am * lda + k0 + aCol);
        As[(aCol + 0) * 128 + aRow] = av.x;
        As[(aCol + 1) * 128 + aRow] = av.y;
        As[(aCol + 2) * 128 + aRow] = av.z;
        As[(aCol + 3) * 128 + aRow] = av.w;

        // --- load B tile into Bs[k][n] ---
        if (!TB) {
            float4 bv = make_float4(0.f, 0.f, 0.f, 0.f);
            int bn = bn0 + bColNN;
            if (bn < N) bv = *(const float4*)(Bb + (size_t)(k0 + bRowNN) * ldb + bn);
            *(float4*)&Bs[bRowNN * 128 + bColNN] = bv;
        } else {
            float4 bv = make_float4(0.f, 0.f, 0.f, 0.f);
            int bn = bn0 + bRowNT;
            if (bn < N) bv = *(const float4*)(Bb + (size_t)bn * ldb + k0 + bColNT);
            Bs[(bColNT + 0) * 128 + bRowNT] = bv.x;
            Bs[(bColNT + 1) * 128 + bRowNT] = bv.y;
            Bs[(bColNT + 2) * 128 + bRowNT] = bv.z;
            Bs[(bColNT + 3) * 128 + bRowNT] = bv.w;
        }
        __syncthreads();

#pragma unroll
        for (int kk = 0; kk < 8; kk++) {
            float4 a0 = *(const float4*)&As[kk * 128 + ty * 8];
            float4 a1 = *(const float4*)&As[kk * 128 + ty * 8 + 4];
            float4 b0 = *(const float4*)&Bs[kk * 128 + tx * 8];
            float4 b1 = *(const float4*)&Bs[kk * 128 + tx * 8 + 4];
            float ar[8] = {a0.x, a0.y, a0.z, a0.w, a1.x, a1.y, a1.z, a1.w};
            float br[8] = {b0.x, b0.y, b0.z, b0.w, b1.x, b1.y, b1.z, b1.w};
#pragma unroll
            for (int r = 0; r < 8; r++)
#pragma unroll
                for (int c = 0; c < 8; c++)
                    acc[r][c] = fmaf(ar[r], br[c], acc[r][c]);
        }
        __syncthreads();
    }

#pragma unroll
    for (int r = 0; r < 8; r++) {
        int m = bm0 + ty * 8 + r;
        if (m >= M) continue;
        float* Crow = Cb + (size_t)m * ldc;
#pragma unroll
        for (int c = 0; c < 8; c++) {
            int n = bn0 + tx * 8 + c;
            if (n >= N) continue;
            float v = acc[r][c];
            if (EPI == 1) v = tanhf(v);
            if (EPI == 2) v += bias[n];
            Crow[n] = v;
        }
    }
}

// ---------------- small prep kernels ----------------
__global__ void k_epad(const int* __restrict__ xs, const float* __restrict__ gembed)
{
    int idx = blockIdx.x * 256 + threadIdx.x;
    if (idx >= BB * 516 * FF) return;
    int f = idx & 255;
    int rest = idx >> 8;
    int ip = rest % 516;
    int b = rest / 516;
    float v = 0.f;
    int i = ip - 2;
    if (i >= 0 && i < NE) {
        int id = xs[b * NE + i];
        v = tanhf(gembed[(size_t)id * FF + f]);
    }
    g_epad[idx] = v;
}

__global__ void k_emb(const int* __restrict__ xs, const int* __restrict__ ys,
                      const float* __restrict__ enc_e, const float* __restrict__ dec_e)
{
    int idx = blockIdx.x * 256 + threadIdx.x;
    if (idx >= BB * NE * EE) return;
    int f = idx & 127;
    int r = idx >> 7;  // b*NE + i
    int xi = xs[r]; if (xi < PP) xi = 0;
    g_xemb[idx] = enc_e[(size_t)xi * EE + f];
    int yi = ys[r]; if (yi < PP) yi = 0;
    g_yemb[idx] = dec_e[(size_t)yi * EE + f];
}

__device__ __forceinline__ unsigned pack_bf2(float a, float b)
{
    unsigned lo = (unsigned)__bfloat16_as_ushort(__float2bfloat16(a));
    unsigned hi = (unsigned)__bfloat16_as_ushort(__float2bfloat16(b));
    return lo | (hi << 16);
}

__global__ void k_pack(const float* __restrict__ We, const float* __restrict__ Wd)
{
    int idx = blockIdx.x * 256 + threadIdx.x;
    if (idx >= 128 * 1024) return;
    int k2 = idx >> 10, n = idx & 1023;
    g_WencP[idx] = pack_bf2(We[n * 256 + 2 * k2], We[n * 256 + 2 * k2 + 1]);
    g_WdecP[idx] = pack_bf2(Wd[n * 256 + 2 * k2], Wd[n * 256 + 2 * k2 + 1]);
}

// ---------------- softmax row stats over vocab ----------------
__global__ void k_rowstats()
{
    int row = blockIdx.x;  // 0 .. B*NE-1
    const float* L = g_logits + (size_t)row * VOC;
    int t = threadIdx.x;  // 256
    __shared__ float red[256];
    float m = -1e30f;
    for (int v = t; v < VOC; v += 256) m = fmaxf(m, L[v]);
    red[t] = m; __syncthreads();
    for (int s = 128; s > 0; s >>= 1) { if (t < s) red[t] = fmaxf(red[t], red[t + s]); __syncthreads(); }
    m = red[0];
    __syncthreads();
    float s = 0.f;
    for (int v = t; v < VOC; v += 256) s += expf(L[v] - m);
    red[t] = s; __syncthreads();
    for (int sr = 128; sr > 0; sr >>= 1) { if (t < sr) red[t] += red[t + sr]; __syncthreads(); }
    if (t == 0) { g_rmax[row] = m; g_rsum[row] = red[0]; }
}

// encoder_scores S[b][j][i] = softmax(logits[b,i,:])[ys[b,j]]
__global__ void k_scores(const int* __restrict__ ys)
{
    int bj = blockIdx.x;      // b*ND + j
    int b = bj >> 9;
    int v = ys[bj];
    int i = threadIdx.x;      // 512
    size_t row = (size_t)b * NE + i;
    float l = g_logits[row * VOC + v];
    g_S[(size_t)bj * NE + i] = expf(l - g_rmax[row]) / g_rsum[row];
}

// ---------------- LSTM persistent kernels ----------------
__device__ __forceinline__ float sigf(float x) { return 1.f / (1.f + expf(-x)); }

__global__ void __launch_bounds__(1024) lstm_enc()
{
    int b = blockIdx.x & 31;
    int dir = blockIdx.x >> 5;  // 0 fwd, 1 bwd
    int n = threadIdx.x;

    __shared__ __align__(16) float hs[256];
    __shared__ float cs[256];
    __shared__ float zs[1024];
    if (n < 256) { hs[n] = 0.f; cs[n] = 0.f; }
    __syncthreads();
    const float2* hs2 = (const float2*)hs;
    const unsigned* __restrict__ w = g_WencP + n;

    for (int t = 0; t < 512; t++) {
        int tt = dir ? (511 - t) : t;
        float acc = g_xz[((size_t)b * NE + tt) * 1024 + n];
#pragma unroll 8
        for (int k2 = 0; k2 < 128; k2++) {
            unsigned u = w[(size_t)k2 * 1024];
            float2 h2 = hs2[k2];
            acc = fmaf(__uint_as_float(u << 16), h2.x, acc);
            acc = fmaf(__uint_as_float(u & 0xffff0000u), h2.y, acc);
        }
        zs[n] = acc;
        __syncthreads();
        if (n < 256) {
            float ig = sigf(zs[n]);
            float fg = sigf(zs[256 + n]);
            float gg = tanhf(zs[512 + n]);
            float og = sigf(zs[768 + n]);
            float c = fg * cs[n] + ig * gg;
            float h = og * tanhf(c);
            cs[n] = c; hs[n] = h;
            g_hcat[((size_t)b * NE + tt) * 512 + dir * 256 + n] = h;
            if (dir == 0 && t == 511) g_cT[b * 256 + n] = c;
        }
        __syncthreads();
    }
}

__global__ void __launch_bounds__(1024) lstm_dec()
{
    int b = blockIdx.x;
    int n = threadIdx.x;

    __shared__ __align__(16) float hs[256];
    __shared__ float cs[256];
    __shared__ float zs[1024];
    if (n < 256) {
        float h0 = g_hcat[((size_t)b * NE + 511) * 512 + n];  // henc final (fwd half)
        hs[n] = h0;
        cs[n] = g_cT[b * 256 + n];
        g_hdec[((size_t)b * ND + 0) * HH + n] = h0;           // h_dec[:,0] = henc[:,-1]
    }
    __syncthreads();
    const float2* hs2 = (const float2*)hs;
    const unsigned* __restrict__ w = g_WdecP + n;

    for (int t = 0; t < 512; t++) {
        float acc = g_yz[((size_t)b * ND + t) * 1024 + n];
#pragma unroll 8
        for (int k2 = 0; k2 < 128; k2++) {
            unsigned u = w[(size_t)k2 * 1024];
            float2 h2 = hs2[k2];
            acc = fmaf(__uint_as_float(u << 16), h2.x, acc);
            acc = fmaf(__uint_as_float(u & 0xffff0000u), h2.y, acc);
        }
        zs[n] = acc;
        __syncthreads();
        if (n < 256) {
            float ig = sigf(zs[n]);
            float fg = sigf(zs[256 + n]);
            float gg = tanhf(zs[512 + n]);
            float og = sigf(zs[768 + n]);
            float c = fg * cs[n] + ig * gg;
            float h = og * tanhf(c);
            cs[n] = c; hs[n] = h;
            if (t < 511) g_hdec[((size_t)b * ND + t + 1) * HH + n] = h;
        }
        __syncthreads();
    }
}

// ---------------- alignment softmax + score mix ----------------
__global__ void k_align()
{
    int bj = blockIdx.x;  // b*ND + j
    const float* E = g_E + (size_t)bj * NE;
    const float* S = g_S + (size_t)bj * NE;
    int t = threadIdx.x;  // 256
    __shared__ float r1[256];
    __shared__ float r2[256];

    float m = -1e30f;
    for (int i = t; i < NE; i += 256) m = fmaxf(m, E[i]);
    r1[t] = m; __syncthreads();
    for (int s = 128; s > 0; s >>= 1) { if (t < s) r1[t] = fmaxf(r1[t], r1[t + s]); __syncthreads(); }
    m = r1[0];
    __syncthreads();

    float s1 = 0.f, s2 = 0.f;
    for (int i = t; i < NE; i += 256) {
        float e = expf(E[i] - m);
        s1 += e;
        s2 += e * S[i];
    }
    r1[t] = s1; r2[t] = s2; __syncthreads();
    for (int s = 128; s > 0; s >>= 1) {
        if (t < s) { r1[t] += r1[t + s]; r2[t] += r2[t + s]; }
        __syncthreads();
    }
    if (t == 0) g_p[bj] = logf(r2[0]) - logf(r1[0]);
}

__global__ void k_final(float* __restrict__ out)
{
    int t = threadIdx.x;  // 1024
    __shared__ float red[1024];
    float s = 0.f;
    for (int i = t; i < BB * ND; i += 1024) s += g_p[i];
    red[t] = s; __syncthreads();
    for (int sr = 512; sr > 0; sr >>= 1) { if (t < sr) red[t] += red[t + sr]; __syncthreads(); }
    if (t == 0) out[0] = -red[0];
}

// ---------------- host launcher ----------------
extern "C" void kernel_launch(void* const* d_in, const int* in_sizes, int n_in,
                              void* d_out, int out_size)
{
    const int*   xs        = (const int*)d_in[0];
    const int*   ys        = (const int*)d_in[1];
    const float* gembed    = (const float*)d_in[2];
    const float* gconv     = (const float*)d_in[3];
    const float* gdecode   = (const float*)d_in[4];
    const float* enc_embed = (const float*)d_in[5];
    const float* dec_embed = (const float*)d_in[6];
    const float* enc_Wih   = (const float*)d_in[7];
    const float* enc_Whh   = (const float*)d_in[8];
    const float* enc_b     = (const float*)d_in[9];
    const float* dec_Wih   = (const float*)d_in[10];
    const float* dec_Whh   = (const float*)d_in[11];
    const float* dec_b     = (const float*)d_in[12];
    const float* Tm        = (const float*)d_in[13];

    float *p_epad, *p_t, *p_logits, *p_xemb, *p_yemb, *p_xz, *p_yz;
    float *p_hcat, *p_hdec, *p_Th, *p_E;
    cudaGetSymbolAddress((void**)&p_epad, g_epad);
    cudaGetSymbolAddress((void**)&p_t, g_t);
    cudaGetSymbolAddress((void**)&p_logits, g_logits);
    cudaGetSymbolAddress((void**)&p_xemb, g_xemb);
    cudaGetSymbolAddress((void**)&p_yemb, g_yemb);
    cudaGetSymbolAddress((void**)&p_xz, g_xz);
    cudaGetSymbolAddress((void**)&p_yz, g_yz);
    cudaGetSymbolAddress((void**)&p_hcat, g_hcat);
    cudaGetSymbolAddress((void**)&p_hdec, g_hdec);
    cudaGetSymbolAddress((void**)&p_Th, g_Th);
    cudaGetSymbolAddress((void**)&p_E, g_E);

    // prep
    k_pack<<<512, 256>>>(enc_Whh, dec_Whh);
    k_epad<<<(BB * 516 * FF + 255) / 256, 256>>>(xs, gembed);
    k_emb<<<(BB * NE * EE + 255) / 256, 256>>>(xs, ys, enc_embed, dec_embed);

    // conv as GEMM per batch: (512 x 1280) @ (1280 x 256), tanh epilogue
    sgemm<1, false><<<dim3(2, 4, BB), 256>>>(p_epad, (size_t)516 * FF, FF,
                                             gconv, 0, FF,
                                             p_t, (size_t)NE * FF, FF,
                                             NE, FF, 5 * FF, nullptr);

    // decode logits: (16384 x 256) @ (256 x 2000)
    sgemm<0, false><<<dim3(16, 128, 1), 256>>>(p_t, 0, FF,
                                               gdecode, 0, VOC,
                                               p_logits, 0, VOC,
                                               BB * NE, VOC, FF, nullptr);
    k_rowstats<<<BB * NE, 256>>>();
    k_scores<<<BB * ND, 512>>>(ys);

    // xz = xemb @ Wih^T + b ; yz likewise
    sgemm<2, true><<<dim3(8, 128, 1), 256>>>(p_xemb, 0, EE,
                                             enc_Wih, 0, EE,
                                             p_xz, 0, 4 * HH,
                                             BB * NE, 4 * HH, EE, enc_b);
    sgemm<2, true><<<dim3(8, 128, 1), 256>>>(p_yemb, 0, EE,
                                             dec_Wih, 0, EE,
                                             p_yz, 0, 4 * HH,
                                             BB * ND, 4 * HH, EE, dec_b);

    // LSTMs
    lstm_enc<<<64, 1024>>>();
    lstm_dec<<<32, 1024>>>();

    // Th = h_enc @ T^T  (per batch, NT)
    sgemm<0, true><<<dim3(2, 4, BB), 256>>>(p_hcat, (size_t)NE * 2 * HH, 2 * HH,
                                            Tm, 0, 2 * HH,
                                            p_Th, (size_t)NE * HH, HH,
                                            NE, HH, 2 * HH, nullptr);

    // E[b][j][i] = h_dec[b][j] . Th[b][i]  (per batch, NT)
    sgemm<0, true><<<dim3(4, 4, BB), 256>>>(p_hdec, (size_t)ND * HH, HH,
                                            p_Th, (size_t)NE * HH, HH,
                                            p_E, (size_t)ND * NE, NE,
                                            ND, NE, HH, nullptr);

    k_align<<<BB * ND, 256>>>();
    k_final<<<1, 1024>>>((float*)d_out);
}

// round 2
// speedup vs baseline: 1.2716x; 1.2716x over previous
#include <cuda_runtime.h>
#include <cuda_bf16.h>
#include <cstdint>
#include <cstddef>

typedef unsigned long long ull;

// Problem constants
#define BB   32
#define NE   512
#define ND   512
#define VOC  2000
#define HH   256
#define FF   256
#define PP   4
#define EE   128

// ---------------- scratch (device globals; no allocations allowed) ----------------
__device__ float    g_epad[(size_t)BB * 516 * FF];        // padded tanh(embed) for conv
__device__ float    g_t[(size_t)BB * NE * FF];            // tanh(conv)
__device__ float    g_logits[(size_t)BB * NE * VOC];      // decode logits
__device__ float    g_rmax[BB * NE];
__device__ float    g_rsum[BB * NE];
__device__ float    g_S[(size_t)BB * ND * NE];            // encoder_scores, layout (b, j, i)
__device__ float    g_xemb[(size_t)BB * NE * EE];
__device__ float    g_yemb[(size_t)BB * ND * EE];
__device__ float    g_xz[(size_t)BB * NE * 4 * HH];       // x @ Wih^T + b
__device__ float    g_yz[(size_t)BB * ND * 4 * HH];
__device__ __align__(16) uint4 g_WencP4[32 * 1024];       // Whh bf16x2-packed, [kk][row]
__device__ __align__(16) uint4 g_WdecP4[32 * 1024];
__device__ float    g_hcat[(size_t)BB * NE * 2 * HH];     // [henc | hback]
__device__ float    g_cT[BB * HH];
__device__ float    g_hdec[(size_t)BB * ND * HH];         // shifted decoder states
__device__ float    g_Th[(size_t)BB * NE * HH];
__device__ float    g_E[(size_t)BB * ND * NE];            // eij, layout (b, j, i)
__device__ float    g_p[BB * ND];

// ---------------- generic fp32 tiled GEMM: C = A @ B (or A @ B^T) ----------------
// 128x128 tile, BK=8, 256 threads, 8x8 per thread.
// EPI: 0 none, 1 tanh, 2 +bias
template <int EPI, bool TB>
__global__ void __launch_bounds__(256) sgemm(
    const float* __restrict__ A, size_t sAz, int lda,
    const float* __restrict__ B, size_t sBz, int ldb,
    float* __restrict__ C, size_t sCz, int ldc,
    int M, int N, int K, const float* __restrict__ bias)
{
    __shared__ __align__(16) float As[8 * 128];
    __shared__ __align__(16) float Bs[8 * 128];

    const float* Ab = A + blockIdx.z * sAz;
    const float* Bb = B + blockIdx.z * sBz;
    float* Cb = C + blockIdx.z * sCz;

    const int bm0 = blockIdx.y * 128;
    const int bn0 = blockIdx.x * 128;
    const int tid = threadIdx.x;
    const int tx = tid & 15, ty = tid >> 4;

    float acc[8][8];
#pragma unroll
    for (int r = 0; r < 8; r++)
#pragma unroll
        for (int c = 0; c < 8; c++) acc[r][c] = 0.f;

    const int aRow = tid >> 1;            // 0..127
    const int aCol = (tid & 1) * 4;       // 0 or 4
    const int bRowNN = tid >> 5;          // 0..7  (k)
    const int bColNN = (tid & 31) * 4;    // 0..124
    const int bRowNT = tid >> 1;          // n 0..127
    const int bColNT = (tid & 1) * 4;     // k 0 or 4

    for (int k0 = 0; k0 < K; k0 += 8) {
        // --- load A tile (transposed into As[k][m]) ---
        float4 av = make_float4(0.f, 0.f, 0.f, 0.f);
        int am = bm0 + aRow;
        if (am < M) av = *(const float4*)(Ab + (size_t)am * lda + k0 + aCol);
        As[(aCol + 0) * 128 + aRow] = av.x;
        As[(aCol + 1) * 128 + aRow] = av.y;
        As[(aCol + 2) * 128 + aRow] = av.z;
        As[(aCol + 3) * 128 + aRow] = av.w;

        // --- load B tile into Bs[k][n] ---
        if (!TB) {
            float4 bv = make_float4(0.f, 0.f, 0.f, 0.f);
            int bn = bn0 + bColNN;
            if (bn < N) bv = *(const float4*)(Bb + (size_t)(k0 + bRowNN) * ldb + bn);
            *(float4*)&Bs[bRowNN * 128 + bColNN] = bv;
        } else {
            float4 bv = make_float4(0.f, 0.f, 0.f, 0.f);
            int bn = bn0 + bRowNT;
            if (bn < N) bv = *(const float4*)(Bb + (size_t)bn * ldb + k0 + bColNT);
            Bs[(bColNT + 0) * 128 + bRowNT] = bv.x;
            Bs[(bColNT + 1) * 128 + bRowNT] = bv.y;
            Bs[(bColNT + 2) * 128 + bRowNT] = bv.z;
            Bs[(bColNT + 3) * 128 + bRowNT] = bv.w;
        }
        __syncthreads();

#pragma unroll
        for (int kk = 0; kk < 8; kk++) {
            float4 a0 = *(const float4*)&As[kk * 128 + ty * 8];
            float4 a1 = *(const float4*)&As[kk * 128 + ty * 8 + 4];
            float4 b0 = *(const float4*)&Bs[kk * 128 + tx * 8];
            float4 b1 = *(const float4*)&Bs[kk * 128 + tx * 8 + 4];
            float ar[8] = {a0.x, a0.y, a0.z, a0.w, a1.x, a1.y, a1.z, a1.w};
            float br[8] = {b0.x, b0.y, b0.z, b0.w, b1.x, b1.y, b1.z, b1.w};
#pragma unroll
            for (int r = 0; r < 8; r++)
#pragma unroll
                for (int c = 0; c < 8; c++)
                    acc[r][c] = fmaf(ar[r], br[c], acc[r][c]);
        }
        __syncthreads();
    }

#pragma unroll
    for (int r = 0; r < 8; r++) {
        int m = bm0 + ty * 8 + r;
        if (m >= M) continue;
        float* Crow = Cb + (size_t)m * ldc;
#pragma unroll
        for (int c = 0; c < 8; c++) {
            int n = bn0 + tx * 8 + c;
            if (n >= N) continue;
            float v = acc[r][c];
            if (EPI == 1) v = tanhf(v);
            if (EPI == 2) v += bias[n];
            Crow[n] = v;
        }
    }
}

// ---------------- small prep kernels ----------------
__global__ void k_epad(const int* __restrict__ xs, const float* __restrict__ gembed)
{
    int idx = blockIdx.x * 256 + threadIdx.x;
    if (idx >= BB * 516 * FF) return;
    int f = idx & 255;
    int rest = idx >> 8;
    int ip = rest % 516;
    int b = rest / 516;
    float v = 0.f;
    int i = ip - 2;
    if (i >= 0 && i < NE) {
        int id = xs[b * NE + i];
        v = tanhf(gembed[(size_t)id * FF + f]);
    }
    g_epad[idx] = v;
}

__global__ void k_emb(const int* __restrict__ xs, const int* __restrict__ ys,
                      const float* __restrict__ enc_e, const float* __restrict__ dec_e)
{
    int idx = blockIdx.x * 256 + threadIdx.x;
    if (idx >= BB * NE * EE) return;
    int f = idx & 127;
    int r = idx >> 7;  // b*NE + i
    int xi = xs[r]; if (xi < PP) xi = 0;
    g_xemb[idx] = enc_e[(size_t)xi * EE + f];
    int yi = ys[r]; if (yi < PP) yi = 0;
    g_yemb[idx] = dec_e[(size_t)yi * EE + f];
}

__device__ __forceinline__ unsigned pack_bf2(float a, float b)
{
    unsigned lo = (unsigned)__bfloat16_as_ushort(__float2bfloat16(a));
    unsigned hi = (unsigned)__bfloat16_as_ushort(__float2bfloat16(b));
    return lo | (hi << 16);
}

// Pack Whh into uint4 tiles: g_W*P4[kk*1024 + n] holds bf16x2 pairs of
// W[n][8kk .. 8kk+7]  (row n of the 1024x256 matrix, k-chunk kk).
__global__ void k_pack(const float* __restrict__ We, const float* __restrict__ Wd)
{
    int idx = blockIdx.x * 256 + threadIdx.x;
    if (idx >= 32 * 1024) return;
    int kk = idx >> 10, n = idx & 1023;
    const float* re = We + (size_t)n * 256 + 8 * kk;
    const float* rd = Wd + (size_t)n * 256 + 8 * kk;
    uint4 ve, vd;
    ve.x = pack_bf2(re[0], re[1]); ve.y = pack_bf2(re[2], re[3]);
    ve.z = pack_bf2(re[4], re[5]); ve.w = pack_bf2(re[6], re[7]);
    vd.x = pack_bf2(rd[0], rd[1]); vd.y = pack_bf2(rd[2], rd[3]);
    vd.z = pack_bf2(rd[4], rd[5]); vd.w = pack_bf2(rd[6], rd[7]);
    g_WencP4[idx] = ve;
    g_WdecP4[idx] = vd;
}

// ---------------- softmax row stats over vocab ----------------
__global__ void k_rowstats()
{
    int row = blockIdx.x;  // 0 .. B*NE-1
    const float* L = g_logits + (size_t)row * VOC;
    int t = threadIdx.x;  // 256
    __shared__ float red[256];
    float m = -1e30f;
    for (int v = t; v < VOC; v += 256) m = fmaxf(m, L[v]);
    red[t] = m; __syncthreads();
    for (int s = 128; s > 0; s >>= 1) { if (t < s) red[t] = fmaxf(red[t], red[t + s]); __syncthreads(); }
    m = red[0];
    __syncthreads();
    float s = 0.f;
    for (int v = t; v < VOC; v += 256) s += expf(L[v] - m);
    red[t] = s; __syncthreads();
    for (int sr = 128; sr > 0; sr >>= 1) { if (t < sr) red[t] += red[t + sr]; __syncthreads(); }
    if (t == 0) { g_rmax[row] = m; g_rsum[row] = red[0]; }
}

// encoder_scores S[b][j][i] = softmax(logits[b,i,:])[ys[b,j]]
__global__ void k_scores(const int* __restrict__ ys)
{
    int bj = blockIdx.x;      // b*ND + j
    int b = bj >> 9;
    int v = ys[bj];
    int i = threadIdx.x;      // 512
    size_t row = (size_t)b * NE + i;
    float l = g_logits[row * VOC + v];
    g_S[(size_t)bj * NE + i] = expf(l - g_rmax[row]) / g_rsum[row];
}

// ---------------- LSTM persistent kernels ----------------
__device__ __forceinline__ float sigf(float x) { return 1.f / (1.f + expf(-x)); }

// packed f32x2 fma
__device__ __forceinline__ void ffma2(ull& acc, ull w, ull h)
{
    asm("fma.rn.f32x2 %0, %1, %2, %0;" : "+l"(acc) : "l"(w), "l"(h));
}
// two floats -> f32x2 (register pair)
__device__ __forceinline__ ull pkf(float a, float b)
{
    ull r; asm("mov.b64 %0, {%1, %2};" : "=l"(r) : "f"(a), "f"(b)); return r;
}
// bf16x2 word -> f32x2 (lo<<16, hi&mask)
__device__ __forceinline__ ull bfp(unsigned u)
{
    ull r;
    asm("mov.b64 %0, {%1, %2};" : "=l"(r) : "r"(u << 16), "r"(u & 0xffff0000u));
    return r;
}
__device__ __forceinline__ float redp(ull v)
{
    float lo = __uint_as_float((unsigned)v);
    float hi = __uint_as_float((unsigned)(v >> 32));
    return lo + hi;
}

// 512 threads; thread t computes gate rows t and t+512.
__global__ void __launch_bounds__(512) lstm_enc()
{
    int b = blockIdx.x & 31;
    int dir = blockIdx.x >> 5;  // 0 fwd, 1 bwd
    int t = threadIdx.x;        // 0..511

    __shared__ __align__(16) float hs[256];
    __shared__ float cs[256];
    __shared__ float zs[1024];
    if (t < 256) { hs[t] = 0.f; cs[t] = 0.f; }
    __syncthreads();
    const float4* hs4 = (const float4*)hs;
    const uint4* __restrict__ w0 = g_WencP4 + t;
    const uint4* __restrict__ w1 = g_WencP4 + t + 512;

    for (int step = 0; step < 512; step++) {
        int tt = dir ? (511 - step) : step;
        const float* xzr = g_xz + ((size_t)b * NE + tt) * 1024;
        float x0 = xzr[t];
        float x1 = xzr[t + 512];

        ull a0 = 0, a1 = 0, c0 = 0, c1 = 0;
#pragma unroll 8
        for (int kk = 0; kk < 32; kk++) {
            uint4 u0 = w0[kk * 1024];
            uint4 u1 = w1[kk * 1024];
            float4 hA = hs4[2 * kk];
            float4 hB = hs4[2 * kk + 1];
            ull h01 = pkf(hA.x, hA.y), h23 = pkf(hA.z, hA.w);
            ull h45 = pkf(hB.x, hB.y), h67 = pkf(hB.z, hB.w);
            ffma2(a0, bfp(u0.x), h01); ffma2(a1, bfp(u0.y), h23);
            ffma2(a0, bfp(u0.z), h45); ffma2(a1, bfp(u0.w), h67);
            ffma2(c0, bfp(u1.x), h01); ffma2(c1, bfp(u1.y), h23);
            ffma2(c0, bfp(u1.z), h45); ffma2(c1, bfp(u1.w), h67);
        }
        zs[t]       = x0 + redp(a0) + redp(a1);
        zs[t + 512] = x1 + redp(c0) + redp(c1);
        __syncthreads();
        if (t < 256) {
            float ig = sigf(zs[t]);
            float fg = sigf(zs[256 + t]);
            float gg = tanhf(zs[512 + t]);
            float og = sigf(zs[768 + t]);
            float c = fg * cs[t] + ig * gg;
            float h = og * tanhf(c);
            cs[t] = c; hs[t] = h;
            g_hcat[((size_t)b * NE + tt) * 512 + dir * 256 + t] = h;
            if (dir == 0 && step == 511) g_cT[b * 256 + t] = c;
        }
        __syncthreads();
    }
}

__global__ void __launch_bounds__(512) lstm_dec()
{
    int b = blockIdx.x;
    int t = threadIdx.x;

    __shared__ __align__(16) float hs[256];
    __shared__ float cs[256];
    __shared__ float zs[1024];
    if (t < 256) {
        float h0 = g_hcat[((size_t)b * NE + 511) * 512 + t];  // henc final (fwd half)
        hs[t] = h0;
        cs[t] = g_cT[b * 256 + t];
        g_hdec[((size_t)b * ND + 0) * HH + t] = h0;           // h_dec[:,0] = henc[:,-1]
    }
    __syncthreads();
    const float4* hs4 = (const float4*)hs;
    const uint4* __restrict__ w0 = g_WdecP4 + t;
    const uint4* __restrict__ w1 = g_WdecP4 + t + 512;

    for (int step = 0; step < 512; step++) {
        const float* yzr = g_yz + ((size_t)b * ND + step) * 1024;
        float x0 = yzr[t];
        float x1 = yzr[t + 512];

        ull a0 = 0, a1 = 0, c0 = 0, c1 = 0;
#pragma unroll 8
        for (int kk = 0; kk < 32; kk++) {
            uint4 u0 = w0[kk * 1024];
            uint4 u1 = w1[kk * 1024];
            float4 hA = hs4[2 * kk];
            float4 hB = hs4[2 * kk + 1];
            ull h01 = pkf(hA.x, hA.y), h23 = pkf(hA.z, hA.w);
            ull h45 = pkf(hB.x, hB.y), h67 = pkf(hB.z, hB.w);
            ffma2(a0, bfp(u0.x), h01); ffma2(a1, bfp(u0.y), h23);
            ffma2(a0, bfp(u0.z), h45); ffma2(a1, bfp(u0.w), h67);
            ffma2(c0, bfp(u1.x), h01); ffma2(c1, bfp(u1.y), h23);
            ffma2(c0, bfp(u1.z), h45); ffma2(c1, bfp(u1.w), h67);
        }
        zs[t]       = x0 + redp(a0) + redp(a1);
        zs[t + 512] = x1 + redp(c0) + redp(c1);
        __syncthreads();
        if (t < 256) {
            float ig = sigf(zs[t]);
            float fg = sigf(zs[256 + t]);
            float gg = tanhf(zs[512 + t]);
            float og = sigf(zs[768 + t]);
            float c = fg * cs[t] + ig * gg;
            float h = og * tanhf(c);
            cs[t] = c; hs[t] = h;
            if (step < 511) g_hdec[((size_t)b * ND + step + 1) * HH + t] = h;
        }
        __syncthreads();
    }
}

// ---------------- alignment softmax + score mix ----------------
__global__ void k_align()
{
    int bj = blockIdx.x;  // b*ND + j
    const float* E = g_E + (size_t)bj * NE;
    const float* S = g_S + (size_t)bj * NE;
    int t = threadIdx.x;  // 256
    __shared__ float r1[256];
    __shared__ float r2[256];

    float m = -1e30f;
    for (int i = t; i < NE; i += 256) m = fmaxf(m, E[i]);
    r1[t] = m; __syncthreads();
    for (int s = 128; s > 0; s >>= 1) { if (t < s) r1[t] = fmaxf(r1[t], r1[t + s]); __syncthreads(); }
    m = r1[0];
    __syncthreads();

    float s1 = 0.f, s2 = 0.f;
    for (int i = t; i < NE; i += 256) {
        float e = expf(E[i] - m);
        s1 += e;
        s2 += e * S[i];
    }
    r1[t] = s1; r2[t] = s2; __syncthreads();
    for (int s = 128; s > 0; s >>= 1) {
        if (t < s) { r1[t] += r1[t + s]; r2[t] += r2[t + s]; }
        __syncthreads();
    }
    if (t == 0) g_p[bj] = logf(r2[0]) - logf(r1[0]);
}

__global__ void k_final(float* __restrict__ out)
{
    int t = threadIdx.x;  // 1024
    __shared__ float red[1024];
    float s = 0.f;
    for (int i = t; i < BB * ND; i += 1024) s += g_p[i];
    red[t] = s; __syncthreads();
    for (int sr = 512; sr > 0; sr >>= 1) { if (t < sr) red[t] += red[t + sr]; __syncthreads(); }
    if (t == 0) out[0] = -red[0];
}

// ---------------- host launcher ----------------
extern "C" void kernel_launch(void* const* d_in, const int* in_sizes, int n_in,
                              void* d_out, int out_size)
{
    const int*   xs        = (const int*)d_in[0];
    const int*   ys        = (const int*)d_in[1];
    const float* gembed    = (const float*)d_in[2];
    const float* gconv     = (const float*)d_in[3];
    const float* gdecode   = (const float*)d_in[4];
    const float* enc_embed = (const float*)d_in[5];
    const float* dec_embed = (const float*)d_in[6];
    const float* enc_Wih   = (const float*)d_in[7];
    const float* enc_Whh   = (const float*)d_in[8];
    const float* enc_b     = (const float*)d_in[9];
    const float* dec_Wih   = (const float*)d_in[10];
    const float* dec_Whh   = (const float*)d_in[11];
    const float* dec_b     = (const float*)d_in[12];
    const float* Tm        = (const float*)d_in[13];

    float *p_epad, *p_t, *p_logits, *p_xemb, *p_yemb, *p_xz, *p_yz;
    float *p_hcat, *p_hdec, *p_Th, *p_E;
    cudaGetSymbolAddress((void**)&p_epad, g_epad);
    cudaGetSymbolAddress((void**)&p_t, g_t);
    cudaGetSymbolAddress((void**)&p_logits, g_logits);
    cudaGetSymbolAddress((void**)&p_xemb, g_xemb);
    cudaGetSymbolAddress((void**)&p_yemb, g_yemb);
    cudaGetSymbolAddress((void**)&p_xz, g_xz);
    cudaGetSymbolAddress((void**)&p_yz, g_yz);
    cudaGetSymbolAddress((void**)&p_hcat, g_hcat);
    cudaGetSymbolAddress((void**)&p_hdec, g_hdec);
    cudaGetSymbolAddress((void**)&p_Th, g_Th);
    cudaGetSymbolAddress((void**)&p_E, g_E);

    // prep
    k_pack<<<128, 256>>>(enc_Whh, dec_Whh);
    k_epad<<<(BB * 516 * FF + 255) / 256, 256>>>(xs, gembed);
    k_emb<<<(BB * NE * EE + 255) / 256, 256>>>(xs, ys, enc_embed, dec_embed);

    // conv as GEMM per batch: (512 x 1280) @ (1280 x 256), tanh epilogue
    sgemm<1, false><<<dim3(2, 4, BB), 256>>>(p_epad, (size_t)516 * FF, FF,
                                             gconv, 0, FF,
                                             p_t, (size_t)NE * FF, FF,
                                             NE, FF, 5 * FF, nullptr);

    // decode logits: (16384 x 256) @ (256 x 2000)
    sgemm<0, false><<<dim3(16, 128, 1), 256>>>(p_t, 0, FF,
                                               gdecode, 0, VOC,
                                               p_logits, 0, VOC,
                                               BB * NE, VOC, FF, nullptr);
    k_rowstats<<<BB * NE, 256>>>();
    k_scores<<<BB * ND, 512>>>(ys);

    // xz = xemb @ Wih^T + b ; yz likewise
    sgemm<2, true><<<dim3(8, 128, 1), 256>>>(p_xemb, 0, EE,
                                             enc_Wih, 0, EE,
                                             p_xz, 0, 4 * HH,
                                             BB * NE, 4 * HH, EE, enc_b);
    sgemm<2, true><<<dim3(8, 128, 1), 256>>>(p_yemb, 0, EE,
                                             dec_Wih, 0, EE,
                                             p_yz, 0, 4 * HH,
                                             BB * ND, 4 * HH, EE, dec_b);

    // LSTMs
    lstm_enc<<<64, 512>>>();
    lstm_dec<<<32, 512>>>();

    // Th = h_enc @ T^T  (per batch, NT)
    sgemm<0, true><<<dim3(2, 4, BB), 256>>>(p_hcat, (size_t)NE * 2 * HH, 2 * HH,
                                            Tm, 0, 2 * HH,
                                            p_Th, (size_t)NE * HH, HH,
                                            NE, HH, 2 * HH, nullptr);

    // E[b][j][i] = h_dec[b][j] . Th[b][i]  (per batch, NT)
    sgemm<0, true><<<dim3(4, 4, BB), 256>>>(p_hdec, (size_t)ND * HH, HH,
                                            p_Th, (size_t)NE * HH, HH,
                                            p_E, (size_t)ND * NE, NE,
                                            ND, NE, HH, nullptr);

    k_align<<<BB * ND, 256>>>();
    k_final<<<1, 1024>>>((float*)d_out);
}

// round 3
// speedup vs baseline: 2.1855x; 1.7187x over previous
#include <cuda_runtime.h>
#include <cuda_bf16.h>
#include <cstdint>
#include <cstddef>

typedef unsigned long long ull;

// Problem constants
#define BB   32
#define NE   512
#define ND   512
#define VOC  2000
#define HH   256
#define FF   256
#define PP   4
#define EE   128

// ---------------- scratch (device globals; no allocations allowed) ----------------
__device__ float    g_epad[(size_t)BB * 516 * FF];        // padded tanh(embed) for conv
__device__ float    g_t[(size_t)BB * NE * FF];            // tanh(conv)
__device__ float    g_logits[(size_t)BB * NE * VOC];      // decode logits
__device__ float    g_rmax[BB * NE];
__device__ float    g_rsum[BB * NE];
__device__ float    g_S[(size_t)BB * ND * NE];            // encoder_scores, layout (b, j, i)
__device__ float    g_xemb[(size_t)BB * NE * EE];
__device__ float    g_yemb[(size_t)BB * ND * EE];
__device__ float    g_xz[(size_t)BB * NE * 4 * HH];       // x @ Wih^T + b
__device__ float    g_yz[(size_t)BB * ND * 4 * HH];
__device__ __align__(16) uint4 g_WencP4[32 * 1024];       // Whh bf16x2-packed, [kk][row]
__device__ __align__(16) uint4 g_WdecP4[32 * 1024];
__device__ float    g_hcat[(size_t)BB * NE * 2 * HH];     // [henc | hback]
__device__ float    g_cT[BB * HH];
__device__ float    g_hdec[(size_t)BB * ND * HH];         // shifted decoder states
__device__ float    g_Th[(size_t)BB * NE * HH];
__device__ float    g_E[(size_t)BB * ND * NE];            // eij, layout (b, j, i)
__device__ float    g_p[BB * ND];

// ---------------- generic fp32 tiled GEMM: C = A @ B (or A @ B^T) ----------------
// 128x128 tile, BK=8, 256 threads, 8x8 per thread.
// EPI: 0 none, 1 tanh, 2 +bias
template <int EPI, bool TB>
__global__ void __launch_bounds__(256) sgemm(
    const float* __restrict__ A, size_t sAz, int lda,
    const float* __restrict__ B, size_t sBz, int ldb,
    float* __restrict__ C, size_t sCz, int ldc,
    int M, int N, int K, const float* __restrict__ bias)
{
    __shared__ __align__(16) float As[8 * 128];
    __shared__ __align__(16) float Bs[8 * 128];

    const float* Ab = A + blockIdx.z * sAz;
    const float* Bb = B + blockIdx.z * sBz;
    float* Cb = C + blockIdx.z * sCz;

    const int bm0 = blockIdx.y * 128;
    const int bn0 = blockIdx.x * 128;
    const int tid = threadIdx.x;
    const int tx = tid & 15, ty = tid >> 4;

    float acc[8][8];
#pragma unroll
    for (int r = 0; r < 8; r++)
#pragma unroll
        for (int c = 0; c < 8; c++) acc[r][c] = 0.f;

    const int aRow = tid >> 1;            // 0..127
    const int aCol = (tid & 1) * 4;       // 0 or 4
    const int bRowNN = tid >> 5;          // 0..7  (k)
    const int bColNN = (tid & 31) * 4;    // 0..124
    const int bRowNT = tid >> 1;          // n 0..127
    const int bColNT = (tid & 1) * 4;     // k 0 or 4

    for (int k0 = 0; k0 < K; k0 += 8) {
        float4 av = make_float4(0.f, 0.f, 0.f, 0.f);
        int am = bm0 + aRow;
        if (am < M) av = *(const float4*)(Ab + (size_t)am * lda + k0 + aCol);
        As[(aCol + 0) * 128 + aRow] = av.x;
        As[(aCol + 1) * 128 + aRow] = av.y;
        As[(aCol + 2) * 128 + aRow] = av.z;
        As[(aCol + 3) * 128 + aRow] = av.w;

        if (!TB) {
            float4 bv = make_float4(0.f, 0.f, 0.f, 0.f);
            int bn = bn0 + bColNN;
            if (bn < N) bv = *(const float4*)(Bb + (size_t)(k0 + bRowNN) * ldb + bn);
            *(float4*)&Bs[bRowNN * 128 + bColNN] = bv;
        } else {
            float4 bv = make_float4(0.f, 0.f, 0.f, 0.f);
            int bn = bn0 + bRowNT;
            if (bn < N) bv = *(const float4*)(Bb + (size_t)bn * ldb + k0 + bColNT);
            Bs[(bColNT + 0) * 128 + bRowNT] = bv.x;
            Bs[(bColNT + 1) * 128 + bRowNT] = bv.y;
            Bs[(bColNT + 2) * 128 + bRowNT] = bv.z;
            Bs[(bColNT + 3) * 128 + bRowNT] = bv.w;
        }
        __syncthreads();

#pragma unroll
        for (int kk = 0; kk < 8; kk++) {
            float4 a0 = *(const float4*)&As[kk * 128 + ty * 8];
            float4 a1 = *(const float4*)&As[kk * 128 + ty * 8 + 4];
            float4 b0 = *(const float4*)&Bs[kk * 128 + tx * 8];
            float4 b1 = *(const float4*)&Bs[kk * 128 + tx * 8 + 4];
            float ar[8] = {a0.x, a0.y, a0.z, a0.w, a1.x, a1.y, a1.z, a1.w};
            float br[8] = {b0.x, b0.y, b0.z, b0.w, b1.x, b1.y, b1.z, b1.w};
#pragma unroll
            for (int r = 0; r < 8; r++)
#pragma unroll
                for (int c = 0; c < 8; c++)
                    acc[r][c] = fmaf(ar[r], br[c], acc[r][c]);
        }
        __syncthreads();
    }

#pragma unroll
    for (int r = 0; r < 8; r++) {
        int m = bm0 + ty * 8 + r;
        if (m >= M) continue;
        float* Crow = Cb + (size_t)m * ldc;
#pragma unroll
        for (int c = 0; c < 8; c++) {
            int n = bn0 + tx * 8 + c;
            if (n >= N) continue;
            float v = acc[r][c];
            if (EPI == 1) v = tanhf(v);
            if (EPI == 2) v += bias[n];
            Crow[n] = v;
        }
    }
}

// ---------------- small prep kernels ----------------
__global__ void k_epad(const int* __restrict__ xs, const float* __restrict__ gembed)
{
    int idx = blockIdx.x * 256 + threadIdx.x;
    if (idx >= BB * 516 * FF) return;
    int f = idx & 255;
    int rest = idx >> 8;
    int ip = rest % 516;
    int b = rest / 516;
    float v = 0.f;
    int i = ip - 2;
    if (i >= 0 && i < NE) {
        int id = xs[b * NE + i];
        v = tanhf(gembed[(size_t)id * FF + f]);
    }
    g_epad[idx] = v;
}

__global__ void k_emb(const int* __restrict__ xs, const int* __restrict__ ys,
                      const float* __restrict__ enc_e, const float* __restrict__ dec_e)
{
    int idx = blockIdx.x * 256 + threadIdx.x;
    if (idx >= BB * NE * EE) return;
    int f = idx & 127;
    int r = idx >> 7;  // b*NE + i
    int xi = xs[r]; if (xi < PP) xi = 0;
    g_xemb[idx] = enc_e[(size_t)xi * EE + f];
    int yi = ys[r]; if (yi < PP) yi = 0;
    g_yemb[idx] = dec_e[(size_t)yi * EE + f];
}

__device__ __forceinline__ unsigned pack_bf2(float a, float b)
{
    unsigned lo = (unsigned)__bfloat16_as_ushort(__float2bfloat16(a));
    unsigned hi = (unsigned)__bfloat16_as_ushort(__float2bfloat16(b));
    return lo | (hi << 16);
}

// Pack Whh into uint4 tiles: g_W*P4[kk*1024 + n] holds bf16x2 pairs of
// W[n][8kk .. 8kk+7]  (row n of the 1024x256 matrix, k-chunk kk).
__global__ void k_pack(const float* __restrict__ We, const float* __restrict__ Wd)
{
    int idx = blockIdx.x * 256 + threadIdx.x;
    if (idx >= 32 * 1024) return;
    int kk = idx >> 10, n = idx & 1023;
    const float* re = We + (size_t)n * 256 + 8 * kk;
    const float* rd = Wd + (size_t)n * 256 + 8 * kk;
    uint4 ve, vd;
    ve.x = pack_bf2(re[0], re[1]); ve.y = pack_bf2(re[2], re[3]);
    ve.z = pack_bf2(re[4], re[5]); ve.w = pack_bf2(re[6], re[7]);
    vd.x = pack_bf2(rd[0], rd[1]); vd.y = pack_bf2(rd[2], rd[3]);
    vd.z = pack_bf2(rd[4], rd[5]); vd.w = pack_bf2(rd[6], rd[7]);
    g_WencP4[idx] = ve;
    g_WdecP4[idx] = vd;
}

// ---------------- softmax row stats over vocab ----------------
__global__ void k_rowstats()
{
    int row = blockIdx.x;  // 0 .. B*NE-1
    const float* L = g_logits + (size_t)row * VOC;
    int t = threadIdx.x;  // 256
    __shared__ float red[256];
    float m = -1e30f;
    for (int v = t; v < VOC; v += 256) m = fmaxf(m, L[v]);
    red[t] = m; __syncthreads();
    for (int s = 128; s > 0; s >>= 1) { if (t < s) red[t] = fmaxf(red[t], red[t + s]); __syncthreads(); }
    m = red[0];
    __syncthreads();
    float s = 0.f;
    for (int v = t; v < VOC; v += 256) s += expf(L[v] - m);
    red[t] = s; __syncthreads();
    for (int sr = 128; sr > 0; sr >>= 1) { if (t < sr) red[t] += red[t + sr]; __syncthreads(); }
    if (t == 0) { g_rmax[row] = m; g_rsum[row] = red[0]; }
}

// encoder_scores S[b][j][i] = softmax(logits[b,i,:])[ys[b,j]]
__global__ void k_scores(const int* __restrict__ ys)
{
    int bj = blockIdx.x;      // b*ND + j
    int b = bj >> 9;
    int v = ys[bj];
    int i = threadIdx.x;      // 512
    size_t row = (size_t)b * NE + i;
    float l = g_logits[row * VOC + v];
    g_S[(size_t)bj * NE + i] = expf(l - g_rmax[row]) / g_rsum[row];
}

// ---------------- LSTM cluster kernels (weights SMEM-resident) ----------------
__device__ __forceinline__ float sigf(float x) { return 1.f / (1.f + expf(-x)); }

__device__ __forceinline__ void ffma2(ull& acc, ull w, ull h)
{
    asm("fma.rn.f32x2 %0, %1, %2, %0;" : "+l"(acc) : "l"(w), "l"(h));
}
// bf16x2 word -> f32x2 pair
__device__ __forceinline__ ull bfp(unsigned u)
{
    ull r;
    asm("mov.b64 %0, {%1, %2};" : "=l"(r) : "r"(u << 16), "r"(u & 0xffff0000u));
    return r;
}
__device__ __forceinline__ float redp(ull v)
{
    float lo = __uint_as_float((unsigned)v);
    float hi = __uint_as_float((unsigned)(v >> 32));
    return lo + hi;
}
__device__ __forceinline__ unsigned smem_u32(const void* p)
{
    unsigned a;
    asm("{ .reg .u64 t; cvta.to.shared.u64 t, %1; cvt.u32.u64 %0, t; }" : "=r"(a) : "l"(p));
    return a;
}
#define CLUSTER_BAR() do { \
    asm volatile("barrier.cluster.arrive.aligned;" ::: "memory"); \
    asm volatile("barrier.cluster.wait.aligned;" ::: "memory"); } while (0)

__device__ __forceinline__ void st_peer_f32(unsigned off, int rank, unsigned val)
{
    unsigned ra;
    asm volatile("mapa.shared::cluster.u32 %0, %1, %2;" : "=r"(ra) : "r"(off), "r"(rank));
    asm volatile("st.shared::cluster.b32 [%0], %1;" :: "r"(ra), "r"(val) : "memory");
}

// Encoder: 32 clusters of 4 CTAs (grid 128). Cluster handles one batch element,
// BOTH directions. CTA rank c owns hidden units [c*64, c*64+64): gate rows
// {g*256 + c*64 + u}. Weights for those 256 rows live in smem (128KB).
// smem layout: ws[32*256] uint4 | hb[2][2][256] f32 | zs[2][256] | cs[2][64]
#define ENC_SMEM (131072 + 4096 + 2048 + 512)
__global__ void __launch_bounds__(256, 1) __cluster_dims__(4, 1, 1) lstm_enc_cl()
{
    extern __shared__ __align__(16) char dsm[];
    uint4* ws = (uint4*)dsm;
    float* hb = (float*)(dsm + 131072);
    float* zs = hb + 1024;
    float* cs = zs + 512;

    unsigned rank; asm("mov.u32 %0, %%cluster_ctarank;" : "=r"(rank));
    int b = blockIdx.x >> 2;
    int t = threadIdx.x;
    int gate = t >> 6, u = t & 63;
    int grow = gate * 256 + (int)(rank << 6) + u;   // global gate row for this thread

    // stage weights: local row r -> global row (r>>6)*256 + rank*64 + (r&63)
    for (int i = t; i < 32 * 256; i += 256) {
        int kk = i >> 8, r = i & 255;
        int gr = (r >> 6) * 256 + (int)(rank << 6) + (r & 63);
        ws[i] = g_WencP4[kk * 1024 + gr];
    }
    if (t < 128) cs[t] = 0.f;
    for (int i = t; i < 1024; i += 256) hb[i] = 0.f;
    __syncthreads();
    CLUSTER_BAR();

    unsigned hb_sh = smem_u32(hb);

    for (int step = 0; step < 512; step++) {
        int ph = step & 1;
        int tf = step, tb = 511 - step;
        float x0 = g_xz[((size_t)b * NE + tf) * 1024 + grow];
        float x1 = g_xz[((size_t)b * NE + tb) * 1024 + grow];
        const longlong2* h0 = (const longlong2*)(hb + ph * 512);
        const longlong2* h1 = (const longlong2*)(hb + ph * 512 + 256);
        ull a0 = 0, a1 = 0, d0 = 0, d1 = 0;
#pragma unroll 8
        for (int kk = 0; kk < 32; kk++) {
            uint4 w = ws[kk * 256 + t];
            ull w0 = bfp(w.x), w1 = bfp(w.y), w2 = bfp(w.z), w3 = bfp(w.w);
            longlong2 pA = h0[2 * kk], pB = h0[2 * kk + 1];
            ffma2(a0, w0, (ull)pA.x); ffma2(a1, w1, (ull)pA.y);
            ffma2(a0, w2, (ull)pB.x); ffma2(a1, w3, (ull)pB.y);
            pA = h1[2 * kk]; pB = h1[2 * kk + 1];
            ffma2(d0, w0, (ull)pA.x); ffma2(d1, w1, (ull)pA.y);
            ffma2(d0, w2, (ull)pB.x); ffma2(d1, w3, (ull)pB.y);
        }
        zs[t]       = x0 + redp(a0) + redp(a1);
        zs[256 + t] = x1 + redp(d0) + redp(d1);
        __syncthreads();
        if (t < 128) {
            int dir = t >> 6, uu = t & 63;
            const float* z = zs + dir * 256;
            float ig = sigf(z[uu]);
            float fg = sigf(z[64 + uu]);
            float gg = tanhf(z[128 + uu]);
            float og = sigf(z[192 + uu]);
            float cc = fg * cs[dir * 64 + uu] + ig * gg;
            float hh = og * tanhf(cc);
            cs[dir * 64 + uu] = cc;
            int tt = dir ? tb : tf;
            g_hcat[((size_t)b * NE + tt) * 512 + dir * 256 + (int)(rank << 6) + uu] = hh;
            if (dir == 0 && step == 511) g_cT[b * 256 + (int)(rank << 6) + uu] = cc;
            unsigned off = hb_sh + ((((ph ^ 1) * 2 + dir) * 256 + (int)(rank << 6) + uu) << 2);
            unsigned hv = __float_as_uint(hh);
            st_peer_f32(off, 0, hv);
            st_peer_f32(off, 1, hv);
            st_peer_f32(off, 2, hv);
            st_peer_f32(off, 3, hv);
        }
        CLUSTER_BAR();
    }
}

// Decoder: same structure, one direction.
// smem: ws 128KB | hb[2][256] | zs[256] | cs[64]
#define DEC_SMEM (131072 + 2048 + 1024 + 256)
__global__ void __launch_bounds__(256, 1) __cluster_dims__(4, 1, 1) lstm_dec_cl()
{
    extern __shared__ __align__(16) char dsm[];
    uint4* ws = (uint4*)dsm;
    float* hb = (float*)(dsm + 131072);
    float* zs = hb + 512;
    float* cs = zs + 256;

    unsigned rank; asm("mov.u32 %0, %%cluster_ctarank;" : "=r"(rank));
    int b = blockIdx.x >> 2;
    int t = threadIdx.x;
    int gate = t >> 6, u = t & 63;
    int grow = gate * 256 + (int)(rank << 6) + u;

    for (int i = t; i < 32 * 256; i += 256) {
        int kk = i >> 8, r = i & 255;
        int gr = (r >> 6) * 256 + (int)(rank << 6) + (r & 63);
        ws[i] = g_WdecP4[kk * 1024 + gr];
    }
    float h0v = g_hcat[((size_t)b * NE + 511) * 512 + t];   // henc final fwd, unit t
    hb[t] = h0v;
    hb[256 + t] = 0.f;
    if (t < 64) cs[t] = g_cT[b * 256 + (int)(rank << 6) + t];
    if (rank == 0) g_hdec[(size_t)b * ND * HH + t] = h0v;   // h_dec[:,0] = henc[:,-1]
    __syncthreads();
    CLUSTER_BAR();

    unsigned hb_sh = smem_u32(hb);

    for (int step = 0; step < 512; step++) {
        int ph = step & 1;
        float x0 = g_yz[((size_t)b * ND + step) * 1024 + grow];
        const longlong2* h0 = (const longlong2*)(hb + ph * 256);
        ull a0 = 0, a1 = 0;
#pragma unroll 8
        for (int kk = 0; kk < 32; kk++) {
            uint4 w = ws[kk * 256 + t];
            longlong2 pA = h0[2 * kk], pB = h0[2 * kk + 1];
            ffma2(a0, bfp(w.x), (ull)pA.x); ffma2(a1, bfp(w.y), (ull)pA.y);
            ffma2(a0, bfp(w.z), (ull)pB.x); ffma2(a1, bfp(w.w), (ull)pB.y);
        }
        zs[t] = x0 + redp(a0) + redp(a1);
        __syncthreads();
        if (t < 64) {
            float ig = sigf(zs[t]);
            float fg = sigf(zs[64 + t]);
            float gg = tanhf(zs[128 + t]);
            float og = sigf(zs[192 + t]);
            float cc = fg * cs[t] + ig * gg;
            float hh = og * tanhf(cc);
            cs[t] = cc;
            if (step < 511)
                g_hdec[((size_t)b * ND + step + 1) * HH + (int)(rank << 6) + t] = hh;
            unsigned off = hb_sh + (((ph ^ 1) * 256 + (int)(rank << 6) + t) << 2);
            unsigned hv = __float_as_uint(hh);
            st_peer_f32(off, 0, hv);
            st_peer_f32(off, 1, hv);
            st_peer_f32(off, 2, hv);
            st_peer_f32(off, 3, hv);
        }
        CLUSTER_BAR();
    }
}

// ---------------- alignment softmax + score mix ----------------
__global__ void k_align()
{
    int bj = blockIdx.x;  // b*ND + j
    const float* E = g_E + (size_t)bj * NE;
    const float* S = g_S + (size_t)bj * NE;
    int t = threadIdx.x;  // 256
    __shared__ float r1[256];
    __shared__ float r2[256];

    float m = -1e30f;
    for (int i = t; i < NE; i += 256) m = fmaxf(m, E[i]);
    r1[t] = m; __syncthreads();
    for (int s = 128; s > 0; s >>= 1) { if (t < s) r1[t] = fmaxf(r1[t], r1[t + s]); __syncthreads(); }
    m = r1[0];
    __syncthreads();

    float s1 = 0.f, s2 = 0.f;
    for (int i = t; i < NE; i += 256) {
        float e = expf(E[i] - m);
        s1 += e;
        s2 += e * S[i];
    }
    r1[t] = s1; r2[t] = s2; __syncthreads();
    for (int s = 128; s > 0; s >>= 1) {
        if (t < s) { r1[t] += r1[t + s]; r2[t] += r2[t + s]; }
        __syncthreads();
    }
    if (t == 0) g_p[bj] = logf(r2[0]) - logf(r1[0]);
}

__global__ void k_final(float* __restrict__ out)
{
    int t = threadIdx.x;  // 1024
    __shared__ float red[1024];
    float s = 0.f;
    for (int i = t; i < BB * ND; i += 1024) s += g_p[i];
    red[t] = s; __syncthreads();
    for (int sr = 512; sr > 0; sr >>= 1) { if (t < sr) red[t] += red[t + sr]; __syncthreads(); }
    if (t == 0) out[0] = -red[0];
}

// ---------------- host launcher ----------------
extern "C" void kernel_launch(void* const* d_in, const int* in_sizes, int n_in,
                              void* d_out, int out_size)
{
    const int*   xs        = (const int*)d_in[0];
    const int*   ys        = (const int*)d_in[1];
    const float* gembed    = (const float*)d_in[2];
    const float* gconv     = (const float*)d_in[3];
    const float* gdecode   = (const float*)d_in[4];
    const float* enc_embed = (const float*)d_in[5];
    const float* dec_embed = (const float*)d_in[6];
    const float* enc_Wih   = (const float*)d_in[7];
    const float* enc_Whh   = (const float*)d_in[8];
    const float* enc_b     = (const float*)d_in[9];
    const float* dec_Wih   = (const float*)d_in[10];
    const float* dec_Whh   = (const float*)d_in[11];
    const float* dec_b     = (const float*)d_in[12];
    const float* Tm        = (const float*)d_in[13];

    float *p_epad, *p_t, *p_logits, *p_xemb, *p_yemb, *p_xz, *p_yz;
    float *p_hcat, *p_hdec, *p_Th, *p_E;
    cudaGetSymbolAddress((void**)&p_epad, g_epad);
    cudaGetSymbolAddress((void**)&p_t, g_t);
    cudaGetSymbolAddress((void**)&p_logits, g_logits);
    cudaGetSymbolAddress((void**)&p_xemb, g_xemb);
    cudaGetSymbolAddress((void**)&p_yemb, g_yemb);
    cudaGetSymbolAddress((void**)&p_xz, g_xz);
    cudaGetSymbolAddress((void**)&p_yz, g_yz);
    cudaGetSymbolAddress((void**)&p_hcat, g_hcat);
    cudaGetSymbolAddress((void**)&p_hdec, g_hdec);
    cudaGetSymbolAddress((void**)&p_Th, g_Th);
    cudaGetSymbolAddress((void**)&p_E, g_E);

    static bool attr_done = false;
    if (!attr_done) {
        cudaFuncSetAttribute(lstm_enc_cl, cudaFuncAttributeMaxDynamicSharedMemorySize, ENC_SMEM);
        cudaFuncSetAttribute(lstm_dec_cl, cudaFuncAttributeMaxDynamicSharedMemorySize, DEC_SMEM);
        attr_done = true;
    }

    // prep
    k_pack<<<128, 256>>>(enc_Whh, dec_Whh);
    k_epad<<<(BB * 516 * FF + 255) / 256, 256>>>(xs, gembed);
    k_emb<<<(BB * NE * EE + 255) / 256, 256>>>(xs, ys, enc_embed, dec_embed);

    // conv as GEMM per batch: (512 x 1280) @ (1280 x 256), tanh epilogue
    sgemm<1, false><<<dim3(2, 4, BB), 256>>>(p_epad, (size_t)516 * FF, FF,
                                             gconv, 0, FF,
                                             p_t, (size_t)NE * FF, FF,
                                             NE, FF, 5 * FF, nullptr);

    // xz = xemb @ Wih^T + b ; yz likewise (needed before LSTMs)
    sgemm<2, true><<<dim3(8, 128, 1), 256>>>(p_xemb, 0, EE,
                                             enc_Wih, 0, EE,
                                             p_xz, 0, 4 * HH,
                                             BB * NE, 4 * HH, EE, enc_b);
    sgemm<2, true><<<dim3(8, 128, 1), 256>>>(p_yemb, 0, EE,
                                             dec_Wih, 0, EE,
                                             p_yz, 0, 4 * HH,
                                             BB * ND, 4 * HH, EE, dec_b);

    // LSTMs (clustered, smem-resident weights)
    lstm_enc_cl<<<128, 256, ENC_SMEM>>>();
    lstm_dec_cl<<<128, 256, DEC_SMEM>>>();

    // decode logits: (16384 x 256) @ (256 x 2000)
    sgemm<0, false><<<dim3(16, 128, 1), 256>>>(p_t, 0, FF,
                                               gdecode, 0, VOC,
                                               p_logits, 0, VOC,
                                               BB * NE, VOC, FF, nullptr);
    k_rowstats<<<BB * NE, 256>>>();
    k_scores<<<BB * ND, 512>>>(ys);

    // Th = h_enc @ T^T  (per batch, NT)
    sgemm<0, true><<<dim3(2, 4, BB), 256>>>(p_hcat, (size_t)NE * 2 * HH, 2 * HH,
                                            Tm, 0, 2 * HH,
                                            p_Th, (size_t)NE * HH, HH,
                                            NE, HH, 2 * HH, nullptr);

    // E[b][j][i] = h_dec[b][j] . Th[b][i]  (per batch, NT)
    sgemm<0, true><<<dim3(4, 4, BB), 256>>>(p_hdec, (size_t)ND * HH, HH,
                                            p_Th, (size_t)NE * HH, HH,
                                            p_E, (size_t)ND * NE, NE,
                                            ND, NE, HH, nullptr);

    k_align<<<BB * ND, 256>>>();
    k_final<<<1, 1024>>>((float*)d_out);
}

// round 4
// speedup vs baseline: 2.3003x; 1.0525x over previous
#include <cuda_runtime.h>
#include <cuda_bf16.h>
#include <cstdint>
#include <cstddef>

typedef unsigned long long ull;

// Problem constants
#define BB   32
#define NE   512
#define ND   512
#define VOC  2000
#define HH   256
#define FF   256
#define PP   4
#define EE   128

// ---------------- scratch (device globals; no allocations allowed) ----------------
__device__ float    g_epad[(size_t)BB * 516 * FF];        // padded tanh(embed) for conv
__device__ float    g_t[(size_t)BB * NE * FF];            // tanh(conv)
__device__ float    g_logits[(size_t)BB * NE * VOC];      // decode logits
__device__ float    g_rmax[BB * NE];
__device__ float    g_rsum[BB * NE];
__device__ float    g_S[(size_t)BB * ND * NE];            // encoder_scores, layout (b, j, i)
__device__ float    g_xemb[(size_t)BB * NE * EE];
__device__ float    g_yemb[(size_t)BB * ND * EE];
__device__ float    g_xz[(size_t)BB * NE * 4 * HH];       // x @ Wih^T + b
__device__ float    g_yz[(size_t)BB * ND * 4 * HH];
__device__ __align__(16) uint4 g_WencP4[32 * 1024];       // Whh bf16x2-packed, [kk][row]
__device__ __align__(16) uint4 g_WdecP4[32 * 1024];
__device__ float    g_hcat[(size_t)BB * NE * 2 * HH];     // [henc | hback]
__device__ float    g_cT[BB * HH];
__device__ float    g_hdec[(size_t)BB * ND * HH];         // shifted decoder states
__device__ float    g_Th[(size_t)BB * NE * HH];
__device__ float    g_E[(size_t)BB * ND * NE];            // eij, layout (b, j, i)
__device__ float    g_p[BB * ND];

// ---------------- packed f32x2 helpers ----------------
__device__ __forceinline__ void ffma2(ull& acc, ull w, ull h)
{
    asm("fma.rn.f32x2 %0, %1, %2, %0;" : "+l"(acc) : "l"(w), "l"(h));
}
__device__ __forceinline__ ull pkf(float a, float b)
{
    ull r; asm("mov.b64 %0, {%1, %2};" : "=l"(r) : "f"(a), "f"(b)); return r;
}
__device__ __forceinline__ ull bfp(unsigned u)
{
    ull r;
    asm("mov.b64 %0, {%1, %2};" : "=l"(r) : "r"(u << 16), "r"(u & 0xffff0000u));
    return r;
}
__device__ __forceinline__ float plo(ull v) { return __uint_as_float((unsigned)v); }
__device__ __forceinline__ float phi(ull v) { return __uint_as_float((unsigned)(v >> 32)); }
__device__ __forceinline__ float redp(ull v) { return plo(v) + phi(v); }

// ---------------- generic fp32 tiled GEMM: C = A @ B (or A @ B^T) ----------------
// 128x128 tile, BK=8, 256 threads, 8x8 per thread, FFMA2 inner loop.
// EPI: 0 none, 1 tanh, 2 +bias
template <int EPI, bool TB>
__global__ void __launch_bounds__(256) sgemm(
    const float* __restrict__ A, size_t sAz, int lda,
    const float* __restrict__ B, size_t sBz, int ldb,
    float* __restrict__ C, size_t sCz, int ldc,
    int M, int N, int K, const float* __restrict__ bias)
{
    __shared__ __align__(16) float As[8 * 128];
    __shared__ __align__(16) float Bs[8 * 128];

    const float* Ab = A + blockIdx.z * sAz;
    const float* Bb = B + blockIdx.z * sBz;
    float* Cb = C + blockIdx.z * sCz;

    const int bm0 = blockIdx.y * 128;
    const int bn0 = blockIdx.x * 128;
    const int tid = threadIdx.x;
    const int tx = tid & 15, ty = tid >> 4;

    // accp[rp][c]: rp indexes m-pairs (m = ty*8 + rp*2 + {0,1} in lo/hi), c = n
    ull accp[4][8];
#pragma unroll
    for (int rp = 0; rp < 4; rp++)
#pragma unroll
        for (int c = 0; c < 8; c++) accp[rp][c] = 0ull;

    const int aRow = tid >> 1;            // 0..127
    const int aCol = (tid & 1) * 4;       // 0 or 4
    const int bRowNN = tid >> 5;          // 0..7  (k)
    const int bColNN = (tid & 31) * 4;    // 0..124
    const int bRowNT = tid >> 1;          // n 0..127
    const int bColNT = (tid & 1) * 4;     // k 0 or 4

    for (int k0 = 0; k0 < K; k0 += 8) {
        float4 av = make_float4(0.f, 0.f, 0.f, 0.f);
        int am = bm0 + aRow;
        if (am < M) av = *(const float4*)(Ab + (size_t)am * lda + k0 + aCol);
        As[(aCol + 0) * 128 + aRow] = av.x;
        As[(aCol + 1) * 128 + aRow] = av.y;
        As[(aCol + 2) * 128 + aRow] = av.z;
        As[(aCol + 3) * 128 + aRow] = av.w;

        if (!TB) {
            float4 bv = make_float4(0.f, 0.f, 0.f, 0.f);
            int bn = bn0 + bColNN;
            if (bn < N) bv = *(const float4*)(Bb + (size_t)(k0 + bRowNN) * ldb + bn);
            *(float4*)&Bs[bRowNN * 128 + bColNN] = bv;
        } else {
            float4 bv = make_float4(0.f, 0.f, 0.f, 0.f);
            int bn = bn0 + bRowNT;
            if (bn < N) bv = *(const float4*)(Bb + (size_t)bn * ldb + k0 + bColNT);
            Bs[(bColNT + 0) * 128 + bRowNT] = bv.x;
            Bs[(bColNT + 1) * 128 + bRowNT] = bv.y;
            Bs[(bColNT + 2) * 128 + bRowNT] = bv.z;
            Bs[(bColNT + 3) * 128 + bRowNT] = bv.w;
        }
        __syncthreads();

#pragma unroll
        for (int kk = 0; kk < 8; kk++) {
            const longlong2* ap = (const longlong2*)&As[kk * 128 + ty * 8];
            longlong2 aA = ap[0], aB = ap[1];
            ull avp[4] = { (ull)aA.x, (ull)aA.y, (ull)aB.x, (ull)aB.y };
            float4 b0 = *(const float4*)&Bs[kk * 128 + tx * 8];
            float4 b1 = *(const float4*)&Bs[kk * 128 + tx * 8 + 4];
            ull bd[8] = { pkf(b0.x, b0.x), pkf(b0.y, b0.y), pkf(b0.z, b0.z), pkf(b0.w, b0.w),
                          pkf(b1.x, b1.x), pkf(b1.y, b1.y), pkf(b1.z, b1.z), pkf(b1.w, b1.w) };
#pragma unroll
            for (int rp = 0; rp < 4; rp++)
#pragma unroll
                for (int c = 0; c < 8; c++)
                    ffma2(accp[rp][c], avp[rp], bd[c]);
        }
        __syncthreads();
    }

#pragma unroll
    for (int rp = 0; rp < 4; rp++) {
#pragma unroll
        for (int half = 0; half < 2; half++) {
            int m = bm0 + ty * 8 + rp * 2 + half;
            if (m >= M) continue;
            float* Crow = Cb + (size_t)m * ldc;
#pragma unroll
            for (int c = 0; c < 8; c++) {
                int n = bn0 + tx * 8 + c;
                if (n >= N) continue;
                float v = half ? phi(accp[rp][c]) : plo(accp[rp][c]);
                if (EPI == 1) v = tanhf(v);
                if (EPI == 2) v += bias[n];
                Crow[n] = v;
            }
        }
    }
}

// ---------------- small prep kernels ----------------
__global__ void k_epad(const int* __restrict__ xs, const float* __restrict__ gembed)
{
    int idx = blockIdx.x * 256 + threadIdx.x;
    if (idx >= BB * 516 * FF) return;
    int f = idx & 255;
    int rest = idx >> 8;
    int ip = rest % 516;
    int b = rest / 516;
    float v = 0.f;
    int i = ip - 2;
    if (i >= 0 && i < NE) {
        int id = xs[b * NE + i];
        v = tanhf(gembed[(size_t)id * FF + f]);
    }
    g_epad[idx] = v;
}

__global__ void k_emb(const int* __restrict__ xs, const int* __restrict__ ys,
                      const float* __restrict__ enc_e, const float* __restrict__ dec_e)
{
    int idx = blockIdx.x * 256 + threadIdx.x;
    if (idx >= BB * NE * EE) return;
    int f = idx & 127;
    int r = idx >> 7;  // b*NE + i
    int xi = xs[r]; if (xi < PP) xi = 0;
    g_xemb[idx] = enc_e[(size_t)xi * EE + f];
    int yi = ys[r]; if (yi < PP) yi = 0;
    g_yemb[idx] = dec_e[(size_t)yi * EE + f];
}

__device__ __forceinline__ unsigned pack_bf2(float a, float b)
{
    unsigned lo = (unsigned)__bfloat16_as_ushort(__float2bfloat16(a));
    unsigned hi = (unsigned)__bfloat16_as_ushort(__float2bfloat16(b));
    return lo | (hi << 16);
}

// Pack Whh into uint4 tiles: g_W*P4[kk*1024 + n] holds bf16x2 pairs of
// W[n][8kk .. 8kk+7]  (row n of the 1024x256 matrix, k-chunk kk).
__global__ void k_pack(const float* __restrict__ We, const float* __restrict__ Wd)
{
    int idx = blockIdx.x * 256 + threadIdx.x;
    if (idx >= 32 * 1024) return;
    int kk = idx >> 10, n = idx & 1023;
    const float* re = We + (size_t)n * 256 + 8 * kk;
    const float* rd = Wd + (size_t)n * 256 + 8 * kk;
    uint4 ve, vd;
    ve.x = pack_bf2(re[0], re[1]); ve.y = pack_bf2(re[2], re[3]);
    ve.z = pack_bf2(re[4], re[5]); ve.w = pack_bf2(re[6], re[7]);
    vd.x = pack_bf2(rd[0], rd[1]); vd.y = pack_bf2(rd[2], rd[3]);
    vd.z = pack_bf2(rd[4], rd[5]); vd.w = pack_bf2(rd[6], rd[7]);
    g_WencP4[idx] = ve;
    g_WdecP4[idx] = vd;
}

// ---------------- softmax row stats over vocab ----------------
__global__ void k_rowstats()
{
    int row = blockIdx.x;  // 0 .. B*NE-1
    const float* L = g_logits + (size_t)row * VOC;
    int t = threadIdx.x;  // 256
    __shared__ float red[256];
    float m = -1e30f;
    for (int v = t; v < VOC; v += 256) m = fmaxf(m, L[v]);
    red[t] = m; __syncthreads();
    for (int s = 128; s > 0; s >>= 1) { if (t < s) red[t] = fmaxf(red[t], red[t + s]); __syncthreads(); }
    m = red[0];
    __syncthreads();
    float s = 0.f;
    for (int v = t; v < VOC; v += 256) s += expf(L[v] - m);
    red[t] = s; __syncthreads();
    for (int sr = 128; sr > 0; sr >>= 1) { if (t < sr) red[t] += red[t + sr]; __syncthreads(); }
    if (t == 0) { g_rmax[row] = m; g_rsum[row] = red[0]; }
}

// encoder_scores S[b][j][i] = softmax(logits[b,i,:])[ys[b,j]]
__global__ void k_scores(const int* __restrict__ ys)
{
    int bj = blockIdx.x;      // b*ND + j
    int b = bj >> 9;
    int v = ys[bj];
    int i = threadIdx.x;      // 512
    size_t row = (size_t)b * NE + i;
    float l = g_logits[row * VOC + v];
    g_S[(size_t)bj * NE + i] = expf(l - g_rmax[row]) / g_rsum[row];
}

// ---------------- LSTM cluster kernels (weights SMEM-resident) ----------------
__device__ __forceinline__ float sigf(float x) { return 1.f / (1.f + expf(-x)); }

__device__ __forceinline__ unsigned smem_u32(const void* p)
{
    unsigned a;
    asm("{ .reg .u64 t; cvta.to.shared.u64 t, %1; cvt.u32.u64 %0, t; }" : "=r"(a) : "l"(p));
    return a;
}
#define CLUSTER_BAR() do { \
    asm volatile("barrier.cluster.arrive.aligned;" ::: "memory"); \
    asm volatile("barrier.cluster.wait.aligned;" ::: "memory"); } while (0)

__device__ __forceinline__ void st_peer_f32(unsigned off, int rank, unsigned val)
{
    unsigned ra;
    asm volatile("mapa.shared::cluster.u32 %0, %1, %2;" : "=r"(ra) : "r"(off), "r"(rank));
    asm volatile("st.shared::cluster.b32 [%0], %1;" :: "r"(ra), "r"(val) : "memory");
}

// Encoder: 32 clusters of 4 CTAs (grid 128). Cluster handles one batch element,
// BOTH directions. CTA rank c owns hidden units [c*64, c*64+64).
// smem layout: ws[32*256] uint4 | hb[2][2][256] f32 | zs[2][256] | cs[2][64]
#define ENC_SMEM (131072 + 4096 + 2048 + 512)
__global__ void __launch_bounds__(256, 1) __cluster_dims__(4, 1, 1) lstm_enc_cl()
{
    extern __shared__ __align__(16) char dsm[];
    uint4* ws = (uint4*)dsm;
    float* hb = (float*)(dsm + 131072);
    float* zs = hb + 1024;
    float* cs = zs + 512;

    unsigned rank; asm("mov.u32 %0, %%cluster_ctarank;" : "=r"(rank));
    int b = blockIdx.x >> 2;
    int t = threadIdx.x;
    int gate = t >> 6, u = t & 63;
    int grow = gate * 256 + (int)(rank << 6) + u;   // global gate row for this thread

    for (int i = t; i < 32 * 256; i += 256) {
        int kk = i >> 8, r = i & 255;
        int gr = (r >> 6) * 256 + (int)(rank << 6) + (r & 63);
        ws[i] = g_WencP4[kk * 1024 + gr];
    }
    if (t < 128) cs[t] = 0.f;
    for (int i = t; i < 1024; i += 256) hb[i] = 0.f;
    __syncthreads();
    CLUSTER_BAR();

    unsigned hb_sh = smem_u32(hb);

    for (int step = 0; step < 512; step++) {
        int ph = step & 1;
        int tf = step, tb = 511 - step;
        float x0 = g_xz[((size_t)b * NE + tf) * 1024 + grow];
        float x1 = g_xz[((size_t)b * NE + tb) * 1024 + grow];
        const longlong2* h0 = (const longlong2*)(hb + ph * 512);
        const longlong2* h1 = (const longlong2*)(hb + ph * 512 + 256);
        ull a0 = 0, a1 = 0, d0 = 0, d1 = 0;
#pragma unroll 8
        for (int kk = 0; kk < 32; kk++) {
            uint4 w = ws[kk * 256 + t];
            ull w0 = bfp(w.x), w1 = bfp(w.y), w2 = bfp(w.z), w3 = bfp(w.w);
            longlong2 pA = h0[2 * kk], pB = h0[2 * kk + 1];
            ffma2(a0, w0, (ull)pA.x); ffma2(a1, w1, (ull)pA.y);
            ffma2(a0, w2, (ull)pB.x); ffma2(a1, w3, (ull)pB.y);
            pA = h1[2 * kk]; pB = h1[2 * kk + 1];
            ffma2(d0, w0, (ull)pA.x); ffma2(d1, w1, (ull)pA.y);
            ffma2(d0, w2, (ull)pB.x); ffma2(d1, w3, (ull)pB.y);
        }
        zs[t]       = x0 + redp(a0) + redp(a1);
        zs[256 + t] = x1 + redp(d0) + redp(d1);
        __syncthreads();
        if (t < 128) {
            int dir = t >> 6, uu = t & 63;
            const float* z = zs + dir * 256;
            float ig = sigf(z[uu]);
            float fg = sigf(z[64 + uu]);
            float gg = tanhf(z[128 + uu]);
            float og = sigf(z[192 + uu]);
            float cc = fg * cs[dir * 64 + uu] + ig * gg;
            float hh = og * tanhf(cc);
            cs[dir * 64 + uu] = cc;
            int tt = dir ? tb : tf;
            g_hcat[((size_t)b * NE + tt) * 512 + dir * 256 + (int)(rank << 6) + uu] = hh;
            if (dir == 0 && step == 511) g_cT[b * 256 + (int)(rank << 6) + uu] = cc;
            unsigned off = hb_sh + ((((ph ^ 1) * 2 + dir) * 256 + (int)(rank << 6) + uu) << 2);
            unsigned hv = __float_as_uint(hh);
            st_peer_f32(off, 0, hv);
            st_peer_f32(off, 1, hv);
            st_peer_f32(off, 2, hv);
            st_peer_f32(off, 3, hv);
        }
        CLUSTER_BAR();
    }
}

// Decoder: same structure, one direction.
// smem: ws 128KB | hb[2][256] | zs[256] | cs[64]
#define DEC_SMEM (131072 + 2048 + 1024 + 256)
__global__ void __launch_bounds__(256, 1) __cluster_dims__(4, 1, 1) lstm_dec_cl()
{
    extern __shared__ __align__(16) char dsm[];
    uint4* ws = (uint4*)dsm;
    float* hb = (float*)(dsm + 131072);
    float* zs = hb + 512;
    float* cs = zs + 256;

    unsigned rank; asm("mov.u32 %0, %%cluster_ctarank;" : "=r"(rank));
    int b = blockIdx.x >> 2;
    int t = threadIdx.x;
    int gate = t >> 6, u = t & 63;
    int grow = gate * 256 + (int)(rank << 6) + u;

    for (int i = t; i < 32 * 256; i += 256) {
        int kk = i >> 8, r = i & 255;
        int gr = (r >> 6) * 256 + (int)(rank << 6) + (r & 63);
        ws[i] = g_WdecP4[kk * 1024 + gr];
    }
    float h0v = g_hcat[((size_t)b * NE + 511) * 512 + t];   // henc final fwd, unit t
    hb[t] = h0v;
    hb[256 + t] = 0.f;
    if (t < 64) cs[t] = g_cT[b * 256 + (int)(rank << 6) + t];
    if (rank == 0) g_hdec[(size_t)b * ND * HH + t] = h0v;   // h_dec[:,0] = henc[:,-1]
    __syncthreads();
    CLUSTER_BAR();

    unsigned hb_sh = smem_u32(hb);

    for (int step = 0; step < 512; step++) {
        int ph = step & 1;
        float x0 = g_yz[((size_t)b * ND + step) * 1024 + grow];
        const longlong2* h0 = (const longlong2*)(hb + ph * 256);
        ull a0 = 0, a1 = 0;
#pragma unroll 8
        for (int kk = 0; kk < 32; kk++) {
            uint4 w = ws[kk * 256 + t];
            longlong2 pA = h0[2 * kk], pB = h0[2 * kk + 1];
            ffma2(a0, bfp(w.x), (ull)pA.x); ffma2(a1, bfp(w.y), (ull)pA.y);
            ffma2(a0, bfp(w.z), (ull)pB.x); ffma2(a1, bfp(w.w), (ull)pB.y);
        }
        zs[t] = x0 + redp(a0) + redp(a1);
        __syncthreads();
        if (t < 64) {
            float ig = sigf(zs[t]);
            float fg = sigf(zs[64 + t]);
            float gg = tanhf(zs[128 + t]);
            float og = sigf(zs[192 + t]);
            float cc = fg * cs[t] + ig * gg;
            float hh = og * tanhf(cc);
            cs[t] = cc;
            if (step < 511)
                g_hdec[((size_t)b * ND + step + 1) * HH + (int)(rank << 6) + t] = hh;
            unsigned off = hb_sh + (((ph ^ 1) * 256 + (int)(rank << 6) + t) << 2);
            unsigned hv = __float_as_uint(hh);
            st_peer_f32(off, 0, hv);
            st_peer_f32(off, 1, hv);
            st_peer_f32(off, 2, hv);
            st_peer_f32(off, 3, hv);
        }
        CLUSTER_BAR();
    }
}

// ---------------- alignment softmax + score mix ----------------
__global__ void k_align()
{
    int bj = blockIdx.x;  // b*ND + j
    const float* E = g_E + (size_t)bj * NE;
    const float* S = g_S + (size_t)bj * NE;
    int t = threadIdx.x;  // 256
    __shared__ float r1[256];
    __shared__ float r2[256];

    float m = -1e30f;
    for (int i = t; i < NE; i += 256) m = fmaxf(m, E[i]);
    r1[t] = m; __syncthreads();
    for (int s = 128; s > 0; s >>= 1) { if (t < s) r1[t] = fmaxf(r1[t], r1[t + s]); __syncthreads(); }
    m = r1[0];
    __syncthreads();

    float s1 = 0.f, s2 = 0.f;
    for (int i = t; i < NE; i += 256) {
        float e = expf(E[i] - m);
        s1 += e;
        s2 += e * S[i];
    }
    r1[t] = s1; r2[t] = s2; __syncthreads();
    for (int s = 128; s > 0; s >>= 1) {
        if (t < s) { r1[t] += r1[t + s]; r2[t] += r2[t + s]; }
        __syncthreads();
    }
    if (t == 0) g_p[bj] = logf(r2[0]) - logf(r1[0]);
}

__global__ void k_final(float* __restrict__ out)
{
    int t = threadIdx.x;  // 1024
    __shared__ float red[1024];
    float s = 0.f;
    for (int i = t; i < BB * ND; i += 1024) s += g_p[i];
    red[t] = s; __syncthreads();
    for (int sr = 512; sr > 0; sr >>= 1) { if (t < sr) red[t] += red[t + sr]; __syncthreads(); }
    if (t == 0) out[0] = -red[0];
}

// ---------------- host launcher ----------------
extern "C" void kernel_launch(void* const* d_in, const int* in_sizes, int n_in,
                              void* d_out, int out_size)
{
    const int*   xs        = (const int*)d_in[0];
    const int*   ys        = (const int*)d_in[1];
    const float* gembed    = (const float*)d_in[2];
    const float* gconv     = (const float*)d_in[3];
    const float* gdecode   = (const float*)d_in[4];
    const float* enc_embed = (const float*)d_in[5];
    const float* dec_embed = (const float*)d_in[6];
    const float* enc_Wih   = (const float*)d_in[7];
    const float* enc_Whh   = (const float*)d_in[8];
    const float* enc_b     = (const float*)d_in[9];
    const float* dec_Wih   = (const float*)d_in[10];
    const float* dec_Whh   = (const float*)d_in[11];
    const float* dec_b     = (const float*)d_in[12];
    const float* Tm        = (const float*)d_in[13];

    float *p_epad, *p_t, *p_logits, *p_xemb, *p_yemb, *p_xz, *p_yz;
    float *p_hcat, *p_hdec, *p_Th, *p_E;
    cudaGetSymbolAddress((void**)&p_epad, g_epad);
    cudaGetSymbolAddress((void**)&p_t, g_t);
    cudaGetSymbolAddress((void**)&p_logits, g_logits);
    cudaGetSymbolAddress((void**)&p_xemb, g_xemb);
    cudaGetSymbolAddress((void**)&p_yemb, g_yemb);
    cudaGetSymbolAddress((void**)&p_xz, g_xz);
    cudaGetSymbolAddress((void**)&p_yz, g_yz);
    cudaGetSymbolAddress((void**)&p_hcat, g_hcat);
    cudaGetSymbolAddress((void**)&p_hdec, g_hdec);
    cudaGetSymbolAddress((void**)&p_Th, g_Th);
    cudaGetSymbolAddress((void**)&p_E, g_E);

    static cudaStream_t s1 = nullptr, s2 = nullptr;
    static cudaEvent_t e0 = nullptr, eg = nullptr, eenc = nullptr, eth = nullptr;
    static bool init_done = false;
    if (!init_done) {
        cudaFuncSetAttribute(lstm_enc_cl, cudaFuncAttributeMaxDynamicSharedMemorySize, ENC_SMEM);
        cudaFuncSetAttribute(lstm_dec_cl, cudaFuncAttributeMaxDynamicSharedMemorySize, DEC_SMEM);
        cudaStreamCreateWithFlags(&s1, cudaStreamNonBlocking);
        cudaStreamCreateWithFlags(&s2, cudaStreamNonBlocking);
        cudaEventCreateWithFlags(&e0, cudaEventDisableTiming);
        cudaEventCreateWithFlags(&eg, cudaEventDisableTiming);
        cudaEventCreateWithFlags(&eenc, cudaEventDisableTiming);
        cudaEventCreateWithFlags(&eth, cudaEventDisableTiming);
        init_done = true;
    }

    // ---- fork: G-equivariant chain on s1 (independent of LSTM chain) ----
    cudaEventRecord(e0, 0);
    cudaStreamWaitEvent(s1, e0, 0);

    k_epad<<<(BB * 516 * FF + 255) / 256, 256, 0, s1>>>(xs, gembed);
    // conv as GEMM per batch: (512 x 1280) @ (1280 x 256), tanh epilogue
    sgemm<1, false><<<dim3(2, 4, BB), 256, 0, s1>>>(p_epad, (size_t)516 * FF, FF,
                                                    gconv, 0, FF,
                                                    p_t, (size_t)NE * FF, FF,
                                                    NE, FF, 5 * FF, nullptr);
    // decode logits: (16384 x 256) @ (256 x 2000)
    sgemm<0, false><<<dim3(16, 128, 1), 256, 0, s1>>>(p_t, 0, FF,
                                                      gdecode, 0, VOC,
                                                      p_logits, 0, VOC,
                                                      BB * NE, VOC, FF, nullptr);
    k_rowstats<<<BB * NE, 256, 0, s1>>>();
    k_scores<<<BB * ND, 512, 0, s1>>>(ys);
    cudaEventRecord(eg, s1);

    // ---- main stream: LSTM chain ----
    k_pack<<<128, 256>>>(enc_Whh, dec_Whh);
    k_emb<<<(BB * NE * EE + 255) / 256, 256>>>(xs, ys, enc_embed, dec_embed);

    // xz = xemb @ Wih^T + b ; yz likewise
    sgemm<2, true><<<dim3(8, 128, 1), 256>>>(p_xemb, 0, EE,
                                             enc_Wih, 0, EE,
                                             p_xz, 0, 4 * HH,
                                             BB * NE, 4 * HH, EE, enc_b);
    sgemm<2, true><<<dim3(8, 128, 1), 256>>>(p_yemb, 0, EE,
                                             dec_Wih, 0, EE,
                                             p_yz, 0, 4 * HH,
                                             BB * ND, 4 * HH, EE, dec_b);

    lstm_enc_cl<<<128, 256, ENC_SMEM>>>();
    cudaEventRecord(eenc, 0);

    // Th = h_enc @ T^T (needs only henc/hback) — overlap with lstm_dec on s2
    cudaStreamWaitEvent(s2, eenc, 0);
    sgemm<0, true><<<dim3(2, 4, BB), 256, 0, s2>>>(p_hcat, (size_t)NE * 2 * HH, 2 * HH,
                                                   Tm, 0, 2 * HH,
                                                   p_Th, (size_t)NE * HH, HH,
                                                   NE, HH, 2 * HH, nullptr);
    cudaEventRecord(eth, s2);

    lstm_dec_cl<<<128, 256, DEC_SMEM>>>();

    // E[b][j][i] = h_dec[b][j] . Th[b][i]
    cudaStreamWaitEvent(0, eth, 0);
    sgemm<0, true><<<dim3(4, 4, BB), 256>>>(p_hdec, (size_t)ND * HH, HH,
                                            p_Th, (size_t)NE * HH, HH,
                                            p_E, (size_t)ND * NE, NE,
                                            ND, NE, HH, nullptr);

    // join G chain, then final mix
    cudaStreamWaitEvent(0, eg, 0);
    k_align<<<BB * ND, 256>>>();
    k_final<<<1, 1024>>>((float*)d_out);
}

// round 5
// speedup vs baseline: 2.8253x; 1.2282x over previous
#include <cuda_runtime.h>
#include <cuda_bf16.h>
#include <cstdint>
#include <cstddef>

typedef unsigned long long ull;

// Problem constants
#define BB   32
#define NE   512
#define ND   512
#define VOC  2000
#define HH   256
#define FF   256
#define PP   4
#define EE   128

// ---------------- scratch (device globals; no allocations allowed) ----------------
__device__ float    g_epad[(size_t)BB * 516 * FF];        // padded tanh(embed) for conv
__device__ float    g_t[(size_t)BB * NE * FF];            // tanh(conv)
__device__ float    g_logits[(size_t)BB * NE * VOC];      // decode logits
__device__ float    g_rmax[BB * NE];
__device__ float    g_rsum[BB * NE];
__device__ float    g_S[(size_t)BB * ND * NE];            // encoder_scores, layout (b, j, i)
__device__ float    g_xemb[(size_t)BB * NE * EE];
__device__ float    g_yemb[(size_t)BB * ND * EE];
__device__ float    g_xz[(size_t)BB * NE * 4 * HH];       // x @ Wih^T + b
__device__ float    g_yz[(size_t)BB * ND * 4 * HH];
__device__ __align__(16) uint4 g_WencP4[32 * 1024];       // Whh bf16x2-packed, [kk][row]
__device__ __align__(16) uint4 g_WdecP4[32 * 1024];
__device__ float    g_hcat[(size_t)BB * NE * 2 * HH];     // [henc | hback]
__device__ float    g_cT[BB * HH];
__device__ float    g_hdec[(size_t)BB * ND * HH];         // shifted decoder states
__device__ float    g_Th[(size_t)BB * NE * HH];
__device__ float    g_E[(size_t)BB * ND * NE];            // eij, layout (b, j, i)
__device__ float    g_p[BB * ND];

// ---------------- packed f32x2 helpers ----------------
__device__ __forceinline__ void ffma2(ull& acc, ull w, ull h)
{
    asm("fma.rn.f32x2 %0, %1, %2, %0;" : "+l"(acc) : "l"(w), "l"(h));
}
__device__ __forceinline__ ull pkf(float a, float b)
{
    ull r; asm("mov.b64 %0, {%1, %2};" : "=l"(r) : "f"(a), "f"(b)); return r;
}
__device__ __forceinline__ float plo(ull v) { return __uint_as_float((unsigned)v); }
__device__ __forceinline__ float phi(ull v) { return __uint_as_float((unsigned)(v >> 32)); }

// ---------------- generic fp32 tiled GEMM: C = A @ B (or A @ B^T) ----------------
// 128x128 tile, BK=8, 256 threads, 8x8 per thread, FFMA2 inner loop.
// EPI: 0 none, 1 tanh, 2 +bias
template <int EPI, bool TB>
__global__ void __launch_bounds__(256) sgemm(
    const float* __restrict__ A, size_t sAz, int lda,
    const float* __restrict__ B, size_t sBz, int ldb,
    float* __restrict__ C, size_t sCz, int ldc,
    int M, int N, int K, const float* __restrict__ bias)
{
    __shared__ __align__(16) float As[8 * 128];
    __shared__ __align__(16) float Bs[8 * 128];

    const float* Ab = A + blockIdx.z * sAz;
    const float* Bb = B + blockIdx.z * sBz;
    float* Cb = C + blockIdx.z * sCz;

    const int bm0 = blockIdx.y * 128;
    const int bn0 = blockIdx.x * 128;
    const int tid = threadIdx.x;
    const int tx = tid & 15, ty = tid >> 4;

    ull accp[4][8];
#pragma unroll
    for (int rp = 0; rp < 4; rp++)
#pragma unroll
        for (int c = 0; c < 8; c++) accp[rp][c] = 0ull;

    const int aRow = tid >> 1;
    const int aCol = (tid & 1) * 4;
    const int bRowNN = tid >> 5;
    const int bColNN = (tid & 31) * 4;
    const int bRowNT = tid >> 1;
    const int bColNT = (tid & 1) * 4;

    for (int k0 = 0; k0 < K; k0 += 8) {
        float4 av = make_float4(0.f, 0.f, 0.f, 0.f);
        int am = bm0 + aRow;
        if (am < M) av = *(const float4*)(Ab + (size_t)am * lda + k0 + aCol);
        As[(aCol + 0) * 128 + aRow] = av.x;
        As[(aCol + 1) * 128 + aRow] = av.y;
        As[(aCol + 2) * 128 + aRow] = av.z;
        As[(aCol + 3) * 128 + aRow] = av.w;

        if (!TB) {
            float4 bv = make_float4(0.f, 0.f, 0.f, 0.f);
            int bn = bn0 + bColNN;
            if (bn < N) bv = *(const float4*)(Bb + (size_t)(k0 + bRowNN) * ldb + bn);
            *(float4*)&Bs[bRowNN * 128 + bColNN] = bv;
        } else {
            float4 bv = make_float4(0.f, 0.f, 0.f, 0.f);
            int bn = bn0 + bRowNT;
            if (bn < N) bv = *(const float4*)(Bb + (size_t)bn * ldb + k0 + bColNT);
            Bs[(bColNT + 0) * 128 + bRowNT] = bv.x;
            Bs[(bColNT + 1) * 128 + bRowNT] = bv.y;
            Bs[(bColNT + 2) * 128 + bRowNT] = bv.z;
            Bs[(bColNT + 3) * 128 + bRowNT] = bv.w;
        }
        __syncthreads();

#pragma unroll
        for (int kk = 0; kk < 8; kk++) {
            const longlong2* ap = (const longlong2*)&As[kk * 128 + ty * 8];
            longlong2 aA = ap[0], aB = ap[1];
            ull avp[4] = { (ull)aA.x, (ull)aA.y, (ull)aB.x, (ull)aB.y };
            float4 b0 = *(const float4*)&Bs[kk * 128 + tx * 8];
            float4 b1 = *(const float4*)&Bs[kk * 128 + tx * 8 + 4];
            ull bd[8] = { pkf(b0.x, b0.x), pkf(b0.y, b0.y), pkf(b0.z, b0.z), pkf(b0.w, b0.w),
                          pkf(b1.x, b1.x), pkf(b1.y, b1.y), pkf(b1.z, b1.z), pkf(b1.w, b1.w) };
#pragma unroll
            for (int rp = 0; rp < 4; rp++)
#pragma unroll
                for (int c = 0; c < 8; c++)
                    ffma2(accp[rp][c], avp[rp], bd[c]);
        }
        __syncthreads();
    }

#pragma unroll
    for (int rp = 0; rp < 4; rp++) {
#pragma unroll
        for (int half = 0; half < 2; half++) {
            int m = bm0 + ty * 8 + rp * 2 + half;
            if (m >= M) continue;
            float* Crow = Cb + (size_t)m * ldc;
#pragma unroll
            for (int c = 0; c < 8; c++) {
                int n = bn0 + tx * 8 + c;
                if (n >= N) continue;
                float v = half ? phi(accp[rp][c]) : plo(accp[rp][c]);
                if (EPI == 1) v = tanhf(v);
                if (EPI == 2) v += bias[n];
                Crow[n] = v;
            }
        }
    }
}

// ---------------- small prep kernels ----------------
__global__ void k_epad(const int* __restrict__ xs, const float* __restrict__ gembed)
{
    int idx = blockIdx.x * 256 + threadIdx.x;
    if (idx >= BB * 516 * FF) return;
    int f = idx & 255;
    int rest = idx >> 8;
    int ip = rest % 516;
    int b = rest / 516;
    float v = 0.f;
    int i = ip - 2;
    if (i >= 0 && i < NE) {
        int id = xs[b * NE + i];
        v = tanhf(gembed[(size_t)id * FF + f]);
    }
    g_epad[idx] = v;
}

__global__ void k_emb(const int* __restrict__ xs, const int* __restrict__ ys,
                      const float* __restrict__ enc_e, const float* __restrict__ dec_e)
{
    int idx = blockIdx.x * 256 + threadIdx.x;
    if (idx >= BB * NE * EE) return;
    int f = idx & 127;
    int r = idx >> 7;
    int xi = xs[r]; if (xi < PP) xi = 0;
    g_xemb[idx] = enc_e[(size_t)xi * EE + f];
    int yi = ys[r]; if (yi < PP) yi = 0;
    g_yemb[idx] = dec_e[(size_t)yi * EE + f];
}

__device__ __forceinline__ unsigned pack_bf2(float a, float b)
{
    unsigned lo = (unsigned)__bfloat16_as_ushort(__float2bfloat16(a));
    unsigned hi = (unsigned)__bfloat16_as_ushort(__float2bfloat16(b));
    return lo | (hi << 16);
}

// g_W*P4[kk*1024 + n] = bf16x2 words of W[n][8kk .. 8kk+7]
__global__ void k_pack(const float* __restrict__ We, const float* __restrict__ Wd)
{
    int idx = blockIdx.x * 256 + threadIdx.x;
    if (idx >= 32 * 1024) return;
    int kk = idx >> 10, n = idx & 1023;
    const float* re = We + (size_t)n * 256 + 8 * kk;
    const float* rd = Wd + (size_t)n * 256 + 8 * kk;
    uint4 ve, vd;
    ve.x = pack_bf2(re[0], re[1]); ve.y = pack_bf2(re[2], re[3]);
    ve.z = pack_bf2(re[4], re[5]); ve.w = pack_bf2(re[6], re[7]);
    vd.x = pack_bf2(rd[0], rd[1]); vd.y = pack_bf2(rd[2], rd[3]);
    vd.z = pack_bf2(rd[4], rd[5]); vd.w = pack_bf2(rd[6], rd[7]);
    g_WencP4[idx] = ve;
    g_WdecP4[idx] = vd;
}

// ---------------- softmax row stats over vocab ----------------
__global__ void k_rowstats()
{
    int row = blockIdx.x;
    const float* L = g_logits + (size_t)row * VOC;
    int t = threadIdx.x;
    __shared__ float red[256];
    float m = -1e30f;
    for (int v = t; v < VOC; v += 256) m = fmaxf(m, L[v]);
    red[t] = m; __syncthreads();
    for (int s = 128; s > 0; s >>= 1) { if (t < s) red[t] = fmaxf(red[t], red[t + s]); __syncthreads(); }
    m = red[0];
    __syncthreads();
    float s = 0.f;
    for (int v = t; v < VOC; v += 256) s += expf(L[v] - m);
    red[t] = s; __syncthreads();
    for (int sr = 128; sr > 0; sr >>= 1) { if (t < sr) red[t] += red[t + sr]; __syncthreads(); }
    if (t == 0) { g_rmax[row] = m; g_rsum[row] = red[0]; }
}

__global__ void k_scores(const int* __restrict__ ys)
{
    int bj = blockIdx.x;
    int b = bj >> 9;
    int v = ys[bj];
    int i = threadIdx.x;
    size_t row = (size_t)b * NE + i;
    float l = g_logits[row * VOC + v];
    g_S[(size_t)bj * NE + i] = expf(l - g_rmax[row]) / g_rsum[row];
}

// ---------------- LSTM: mma.sync + register-stationary weights + cluster ----------------
__device__ __forceinline__ float sigf(float x) { return 1.f / (1.f + expf(-x)); }

__device__ __forceinline__ unsigned smem_u32(const void* p)
{
    unsigned a;
    asm("{ .reg .u64 t; cvta.to.shared.u64 t, %1; cvt.u32.u64 %0, t; }" : "=r"(a) : "l"(p));
    return a;
}
#define CLUSTER_BAR() do { \
    asm volatile("barrier.cluster.arrive.aligned;" ::: "memory"); \
    asm volatile("barrier.cluster.wait.aligned;" ::: "memory"); } while (0)

__device__ __forceinline__ void st_peer_b16(unsigned off, int rank, unsigned short v)
{
    unsigned ra;
    asm volatile("mapa.shared::cluster.u32 %0, %1, %2;" : "=r"(ra) : "r"(off), "r"(rank));
    asm volatile("st.shared::cluster.b16 [%0], %1;" :: "r"(ra), "h"(v) : "memory");
}

__device__ __forceinline__ void mma16816(float& c0, float& c1, float& c2, float& c3,
                                         unsigned a0, unsigned a1, unsigned a2, unsigned a3,
                                         unsigned b0, unsigned b1)
{
    asm("mma.sync.aligned.m16n8k16.row.col.f32.bf16.bf16.f32 "
        "{%0,%1,%2,%3}, {%4,%5,%6,%7}, {%8,%9}, {%0,%1,%2,%3};"
        : "+f"(c0), "+f"(c1), "+f"(c2), "+f"(c3)
        : "r"(a0), "r"(a1), "r"(a2), "r"(a3), "r"(b0), "r"(b1));
}

// h buffer layout: s_h[buf(2)][col(8)][132 words]; col = B-fragment column.
// Only cols 0..NDIR-1 carry h (256 bf16 = 128 words); others are never read usefully.
#define HCOLW 132

// Encoder: 32 clusters x 4 CTAs x 512 threads. Cluster = one batch, both dirs.
// Warp w owns local rows [16w, 16w+16) (local row r = gate*64 + unit).
__global__ void __launch_bounds__(512, 1) __cluster_dims__(4, 1, 1) lstm_enc_mma()
{
    __shared__ unsigned s_h[2 * 8 * HCOLW];
    __shared__ float s_x[512];
    __shared__ float s_z[512];
    __shared__ float s_c[128];

    unsigned rank; asm("mov.u32 %0, %%cluster_ctarank;" : "=r"(rank));
    int b = blockIdx.x >> 2;
    int t = threadIdx.x;
    int w = t >> 5, lane = t & 31, g = lane >> 2, t4 = lane & 3;
    int r1 = 16 * w + g, r2 = r1 + 8;
    int R1 = ((r1 >> 6) << 8) + (int)(rank << 6) + (r1 & 63);
    int R2 = ((r2 >> 6) << 8) + (int)(rank << 6) + (r2 & 63);

    // stationary A fragments (64 regs of bf16x2 weights)
    unsigned areg[64];
    const unsigned* WP = (const unsigned*)g_WencP4;
#pragma unroll
    for (int kt = 0; kt < 16; kt++) {
        areg[4 * kt + 0] = WP[(((2 * kt) * 1024 + R1) << 2) + t4];
        areg[4 * kt + 1] = WP[(((2 * kt) * 1024 + R2) << 2) + t4];
        areg[4 * kt + 2] = WP[(((2 * kt + 1) * 1024 + R1) << 2) + t4];
        areg[4 * kt + 3] = WP[(((2 * kt + 1) * 1024 + R2) << 2) + t4];
    }

    // zero h buf0 cols 0,1 (h=0 initial state)
    for (int i = t; i < 2 * HCOLW; i += 512) s_h[i] = 0;
    if (t < 128) s_c[t] = 0.f;
    __syncthreads();
    CLUSTER_BAR();

    unsigned h_sh = smem_u32(s_h);

    for (int step = 0; step < 512; step++) {
        int ph = step & 1;
        int tf = step, tb = 511 - step;
        // prefetch x (both dirs) for this CTA's 256 rows
        {
            int d = t >> 8, r = t & 255;
            int Gr = ((r >> 6) << 8) + (int)(rank << 6) + (r & 63);
            int tm = d ? tb : tf;
            s_x[t] = g_xz[((size_t)b * NE + tm) * 1024 + Gr];
        }
        // z = Whh @ [h_fwd | h_bwd]  via 16 k-tiles of m16n8k16
        float e0 = 0.f, e1 = 0.f, e2 = 0.f, e3 = 0.f;
        float o0 = 0.f, o1 = 0.f, o2 = 0.f, o3 = 0.f;
        const unsigned* hw = s_h + ph * 8 * HCOLW + g * HCOLW;
#pragma unroll
        for (int kt = 0; kt < 16; kt += 2) {
            unsigned b0 = hw[8 * kt + t4];
            unsigned b1 = hw[8 * kt + t4 + 4];
            mma16816(e0, e1, e2, e3, areg[4 * kt], areg[4 * kt + 1], areg[4 * kt + 2], areg[4 * kt + 3], b0, b1);
            unsigned b2 = hw[8 * (kt + 1) + t4];
            unsigned b3 = hw[8 * (kt + 1) + t4 + 4];
            mma16816(o0, o1, o2, o3, areg[4 * kt + 4], areg[4 * kt + 5], areg[4 * kt + 6], areg[4 * kt + 7], b2, b3);
        }
        if (t4 == 0) {
            s_z[r1] = e0 + o0; s_z[256 + r1] = e1 + o1;
            s_z[r2] = e2 + o2; s_z[256 + r2] = e3 + o3;
        }
        __syncthreads();
        if (t < 128) {
            int d = t >> 6, u = t & 63;
            const float* z = s_z + d * 256;
            const float* x = s_x + d * 256;
            float zi = z[u] + x[u];
            float zf = z[64 + u] + x[64 + u];
            float zg = z[128 + u] + x[128 + u];
            float zo = z[192 + u] + x[192 + u];
            float cc = sigf(zf) * s_c[d * 64 + u] + sigf(zi) * tanhf(zg);
            float hh = sigf(zo) * tanhf(cc);
            s_c[d * 64 + u] = cc;
            int tt = d ? tb : tf;
            g_hcat[((size_t)b * NE + tt) * 512 + d * 256 + (int)(rank << 6) + u] = hh;
            if (d == 0 && step == 511) g_cT[b * 256 + (int)(rank << 6) + u] = cc;
            unsigned short h16 = __bfloat16_as_ushort(__float2bfloat16(hh));
            unsigned off = h_sh + ((unsigned)(((ph ^ 1) * 8 + d) * HCOLW) << 2)
                               + (((unsigned)(rank << 6) + (unsigned)u) << 1);
            st_peer_b16(off, 0, h16);
            st_peer_b16(off, 1, h16);
            st_peer_b16(off, 2, h16);
            st_peer_b16(off, 3, h16);
        }
        CLUSTER_BAR();
    }
}

// Decoder: one direction; h0/c0 from encoder final state.
__global__ void __launch_bounds__(512, 1) __cluster_dims__(4, 1, 1) lstm_dec_mma()
{
    __shared__ unsigned s_h[2 * 8 * HCOLW];
    __shared__ float s_x[256];
    __shared__ float s_z[256];
    __shared__ float s_c[64];

    unsigned rank; asm("mov.u32 %0, %%cluster_ctarank;" : "=r"(rank));
    int b = blockIdx.x >> 2;
    int t = threadIdx.x;
    int w = t >> 5, lane = t & 31, g = lane >> 2, t4 = lane & 3;
    int r1 = 16 * w + g, r2 = r1 + 8;
    int R1 = ((r1 >> 6) << 8) + (int)(rank << 6) + (r1 & 63);
    int R2 = ((r2 >> 6) << 8) + (int)(rank << 6) + (r2 & 63);

    unsigned areg[64];
    const unsigned* WP = (const unsigned*)g_WdecP4;
#pragma unroll
    for (int kt = 0; kt < 16; kt++) {
        areg[4 * kt + 0] = WP[(((2 * kt) * 1024 + R1) << 2) + t4];
        areg[4 * kt + 1] = WP[(((2 * kt) * 1024 + R2) << 2) + t4];
        areg[4 * kt + 2] = WP[(((2 * kt + 1) * 1024 + R1) << 2) + t4];
        areg[4 * kt + 3] = WP[(((2 * kt + 1) * 1024 + R2) << 2) + t4];
    }

    // init: h0 = henc final (bf16 into buf0 col0), c0 from g_cT
    if (t < 256) {
        float hv = g_hcat[((size_t)b * NE + 511) * 512 + t];
        ((unsigned short*)s_h)[t] = __bfloat16_as_ushort(__float2bfloat16(hv));
        if (rank == 0) g_hdec[(size_t)b * ND * HH + t] = hv;
    }
    if (t < 64) s_c[t] = g_cT[b * 256 + (int)(rank << 6) + t];
    __syncthreads();
    CLUSTER_BAR();

    unsigned h_sh = smem_u32(s_h);

    for (int step = 0; step < 512; step++) {
        int ph = step & 1;
        if (t < 256) {
            int Gr = ((t >> 6) << 8) + (int)(rank << 6) + (t & 63);
            s_x[t] = g_yz[((size_t)b * ND + step) * 1024 + Gr];
        }
        float e0 = 0.f, e1 = 0.f, e2 = 0.f, e3 = 0.f;
        float o0 = 0.f, o1 = 0.f, o2 = 0.f, o3 = 0.f;
        const unsigned* hw = s_h + ph * 8 * HCOLW + g * HCOLW;
#pragma unroll
        for (int kt = 0; kt < 16; kt += 2) {
            unsigned b0 = hw[8 * kt + t4];
            unsigned b1 = hw[8 * kt + t4 + 4];
            mma16816(e0, e1, e2, e3, areg[4 * kt], areg[4 * kt + 1], areg[4 * kt + 2], areg[4 * kt + 3], b0, b1);
            unsigned b2 = hw[8 * (kt + 1) + t4];
            unsigned b3 = hw[8 * (kt + 1) + t4 + 4];
            mma16816(o0, o1, o2, o3, areg[4 * kt + 4], areg[4 * kt + 5], areg[4 * kt + 6], areg[4 * kt + 7], b2, b3);
        }
        if (t4 == 0) {
            s_z[r1] = e0 + o0;
            s_z[r2] = e2 + o2;
        }
        __syncthreads();
        if (t < 64) {
            int u = t;
            float zi = s_z[u] + s_x[u];
            float zf = s_z[64 + u] + s_x[64 + u];
            float zg = s_z[128 + u] + s_x[128 + u];
            float zo = s_z[192 + u] + s_x[192 + u];
            float cc = sigf(zf) * s_c[u] + sigf(zi) * tanhf(zg);
            float hh = sigf(zo) * tanhf(cc);
            s_c[u] = cc;
            if (step < 511)
                g_hdec[((size_t)b * ND + step + 1) * HH + (int)(rank << 6) + u] = hh;
            unsigned short h16 = __bfloat16_as_ushort(__float2bfloat16(hh));
            unsigned off = h_sh + ((unsigned)((ph ^ 1) * 8 * HCOLW) << 2)
                               + (((unsigned)(rank << 6) + (unsigned)u) << 1);
            st_peer_b16(off, 0, h16);
            st_peer_b16(off, 1, h16);
            st_peer_b16(off, 2, h16);
            st_peer_b16(off, 3, h16);
        }
        CLUSTER_BAR();
    }
}

// ---------------- alignment softmax + score mix ----------------
__global__ void k_align()
{
    int bj = blockIdx.x;
    const float* E = g_E + (size_t)bj * NE;
    const float* S = g_S + (size_t)bj * NE;
    int t = threadIdx.x;
    __shared__ float r1[256];
    __shared__ float r2[256];

    float m = -1e30f;
    for (int i = t; i < NE; i += 256) m = fmaxf(m, E[i]);
    r1[t] = m; __syncthreads();
    for (int s = 128; s > 0; s >>= 1) { if (t < s) r1[t] = fmaxf(r1[t], r1[t + s]); __syncthreads(); }
    m = r1[0];
    __syncthreads();

    float s1 = 0.f, s2 = 0.f;
    for (int i = t; i < NE; i += 256) {
        float e = expf(E[i] - m);
        s1 += e;
        s2 += e * S[i];
    }
    r1[t] = s1; r2[t] = s2; __syncthreads();
    for (int s = 128; s > 0; s >>= 1) {
        if (t < s) { r1[t] += r1[t + s]; r2[t] += r2[t + s]; }
        __syncthreads();
    }
    if (t == 0) g_p[bj] = logf(r2[0]) - logf(r1[0]);
}

__global__ void k_final(float* __restrict__ out)
{
    int t = threadIdx.x;
    __shared__ float red[1024];
    float s = 0.f;
    for (int i = t; i < BB * ND; i += 1024) s += g_p[i];
    red[t] = s; __syncthreads();
    for (int sr = 512; sr > 0; sr >>= 1) { if (t < sr) red[t] += red[t + sr]; __syncthreads(); }
    if (t == 0) out[0] = -red[0];
}

// ---------------- host launcher ----------------
extern "C" void kernel_launch(void* const* d_in, const int* in_sizes, int n_in,
                              void* d_out, int out_size)
{
    const int*   xs        = (const int*)d_in[0];
    const int*   ys        = (const int*)d_in[1];
    const float* gembed    = (const float*)d_in[2];
    const float* gconv     = (const float*)d_in[3];
    const float* gdecode   = (const float*)d_in[4];
    const float* enc_embed = (const float*)d_in[5];
    const float* dec_embed = (const float*)d_in[6];
    const float* enc_Wih   = (const float*)d_in[7];
    const float* enc_Whh   = (const float*)d_in[8];
    const float* enc_b     = (const float*)d_in[9];
    const float* dec_Wih   = (const float*)d_in[10];
    const float* dec_Whh   = (const float*)d_in[11];
    const float* dec_b     = (const float*)d_in[12];
    const float* Tm        = (const float*)d_in[13];

    float *p_epad, *p_t, *p_logits, *p_xemb, *p_yemb, *p_xz, *p_yz;
    float *p_hcat, *p_hdec, *p_Th, *p_E;
    cudaGetSymbolAddress((void**)&p_epad, g_epad);
    cudaGetSymbolAddress((void**)&p_t, g_t);
    cudaGetSymbolAddress((void**)&p_logits, g_logits);
    cudaGetSymbolAddress((void**)&p_xemb, g_xemb);
    cudaGetSymbolAddress((void**)&p_yemb, g_yemb);
    cudaGetSymbolAddress((void**)&p_xz, g_xz);
    cudaGetSymbolAddress((void**)&p_yz, g_yz);
    cudaGetSymbolAddress((void**)&p_hcat, g_hcat);
    cudaGetSymbolAddress((void**)&p_hdec, g_hdec);
    cudaGetSymbolAddress((void**)&p_Th, g_Th);
    cudaGetSymbolAddress((void**)&p_E, g_E);

    static cudaStream_t s1 = nullptr, s2 = nullptr;
    static cudaEvent_t e0 = nullptr, eg = nullptr, eenc = nullptr, eth = nullptr;
    static bool init_done = false;
    if (!init_done) {
        cudaStreamCreateWithFlags(&s1, cudaStreamNonBlocking);
        cudaStreamCreateWithFlags(&s2, cudaStreamNonBlocking);
        cudaEventCreateWithFlags(&e0, cudaEventDisableTiming);
        cudaEventCreateWithFlags(&eg, cudaEventDisableTiming);
        cudaEventCreateWithFlags(&eenc, cudaEventDisableTiming);
        cudaEventCreateWithFlags(&eth, cudaEventDisableTiming);
        init_done = true;
    }

    // ---- fork: G-equivariant chain on s1 (independent of LSTM chain) ----
    cudaEventRecord(e0, 0);
    cudaStreamWaitEvent(s1, e0, 0);

    k_epad<<<(BB * 516 * FF + 255) / 256, 256, 0, s1>>>(xs, gembed);
    sgemm<1, false><<<dim3(2, 4, BB), 256, 0, s1>>>(p_epad, (size_t)516 * FF, FF,
                                                    gconv, 0, FF,
                                                    p_t, (size_t)NE * FF, FF,
                                                    NE, FF, 5 * FF, nullptr);
    sgemm<0, false><<<dim3(16, 128, 1), 256, 0, s1>>>(p_t, 0, FF,
                                                      gdecode, 0, VOC,
                                                      p_logits, 0, VOC,
                                                      BB * NE, VOC, FF, nullptr);
    k_rowstats<<<BB * NE, 256, 0, s1>>>();
    k_scores<<<BB * ND, 512, 0, s1>>>(ys);
    cudaEventRecord(eg, s1);

    // ---- main stream: LSTM chain ----
    k_pack<<<128, 256>>>(enc_Whh, dec_Whh);
    k_emb<<<(BB * NE * EE + 255) / 256, 256>>>(xs, ys, enc_embed, dec_embed);

    sgemm<2, true><<<dim3(8, 128, 1), 256>>>(p_xemb, 0, EE,
                                             enc_Wih, 0, EE,
                                             p_xz, 0, 4 * HH,
                                             BB * NE, 4 * HH, EE, enc_b);
    sgemm<2, true><<<dim3(8, 128, 1), 256>>>(p_yemb, 0, EE,
                                             dec_Wih, 0, EE,
                                             p_yz, 0, 4 * HH,
                                             BB * ND, 4 * HH, EE, dec_b);

    lstm_enc_mma<<<128, 512>>>();
    cudaEventRecord(eenc, 0);

    // Th = h_enc @ T^T — overlap with lstm_dec on s2
    cudaStreamWaitEvent(s2, eenc, 0);
    sgemm<0, true><<<dim3(2, 4, BB), 256, 0, s2>>>(p_hcat, (size_t)NE * 2 * HH, 2 * HH,
                                                   Tm, 0, 2 * HH,
                                                   p_Th, (size_t)NE * HH, HH,
                                                   NE, HH, 2 * HH, nullptr);
    cudaEventRecord(eth, s2);

    lstm_dec_mma<<<128, 512>>>();

    // E[b][j][i] = h_dec[b][j] . Th[b][i]
    cudaStreamWaitEvent(0, eth, 0);
    sgemm<0, true><<<dim3(4, 4, BB), 256>>>(p_hdec, (size_t)ND * HH, HH,
                                            p_Th, (size_t)NE * HH, HH,
                                            p_E, (size_t)ND * NE, NE,
                                            ND, NE, HH, nullptr);

    cudaStreamWaitEvent(0, eg, 0);
    k_align<<<BB * ND, 256>>>();
    k_final<<<1, 1024>>>((float*)d_out);
}